// round 2
// baseline (speedup 1.0000x reference)
#include <cuda_runtime.h>
#include <math.h>
#include <stdint.h>

#define Bsz   8192
#define DIN   1024
#define Hdim  128
#define Ecnt  8
#define DOUT  1024
#define BKSEL 2048   // ceil(K*B/E) = ceil(2*8192/8)

// ---------------- scratch (device globals; no runtime allocation) ----------
__device__ float g_h[Bsz * Hdim];            // 4 MB  router hidden
__device__ float g_logits[Bsz * Ecnt];       // 256 KB
__device__ int   g_idx[Ecnt][BKSEL];         // selected token index per (e, slot)
__device__ float g_nws[Ecnt][BKSEL];         // renormalized weights
__device__ int   g_sel_slot[Bsz][Ecnt];      // token,expert -> slot or -1
__device__ float g_eo[(size_t)BKSEL * Ecnt * DOUT]; // 64 MB  [slot][e][d]

// ---------------------------------------------------------------------------
// Kernel 1: router hidden h = relu((x@w1+b1) * relu(x@wg+bg))
// 64-row x 128-col tile per block, 256 threads, thread tile 4x8 per matrix.
// ---------------------------------------------------------------------------
__global__ __launch_bounds__(256) void k_router(
    const float* __restrict__ x,
    const float* __restrict__ w1, const float* __restrict__ b1,
    const float* __restrict__ wg, const float* __restrict__ bg)
{
    __shared__ float Xs[16][64];
    __shared__ float W1s[16][128];
    __shared__ float WGs[16][128];

    const int tid = threadIdx.x;
    const int tx  = tid & 15;     // col lane
    const int ty  = tid >> 4;     // row lane
    const int row0 = blockIdx.x * 64;

    float acc1[4][8];
    float accg[4][8];
#pragma unroll
    for (int i = 0; i < 4; i++)
#pragma unroll
        for (int j = 0; j < 8; j++) { acc1[i][j] = 0.f; accg[i][j] = 0.f; }

    for (int k0 = 0; k0 < DIN; k0 += 16) {
        // X tile: 64 rows x 16 k = 1024 floats -> 256 threads x 1 float4
        {
            int lin = tid;
            int m  = lin >> 2;
            int kq = (lin & 3) << 2;
            float4 v = *(const float4*)(x + (size_t)(row0 + m) * DIN + k0 + kq);
            Xs[kq + 0][m] = v.x; Xs[kq + 1][m] = v.y;
            Xs[kq + 2][m] = v.z; Xs[kq + 3][m] = v.w;
        }
        // W tiles: 16 x 128 each = 512 float4 -> 2 per thread
#pragma unroll
        for (int r = 0; r < 2; r++) {
            int lin = tid + r * 256;
            int kk  = lin >> 5;
            int nq  = (lin & 31) << 2;
            *(float4*)&W1s[kk][nq] = *(const float4*)(w1 + (size_t)(k0 + kk) * Hdim + nq);
            *(float4*)&WGs[kk][nq] = *(const float4*)(wg + (size_t)(k0 + kk) * Hdim + nq);
        }
        __syncthreads();
#pragma unroll
        for (int kk = 0; kk < 16; kk++) {
            float xr[4], w1r[8], wgr[8];
#pragma unroll
            for (int i = 0; i < 4; i++) xr[i] = Xs[kk][i * 16 + ty];
#pragma unroll
            for (int j = 0; j < 8; j++) {
                w1r[j] = W1s[kk][j * 16 + tx];
                wgr[j] = WGs[kk][j * 16 + tx];
            }
#pragma unroll
            for (int i = 0; i < 4; i++)
#pragma unroll
                for (int j = 0; j < 8; j++) {
                    acc1[i][j] = fmaf(xr[i], w1r[j], acc1[i][j]);
                    accg[i][j] = fmaf(xr[i], wgr[j], accg[i][j]);
                }
        }
        __syncthreads();
    }
#pragma unroll
    for (int i = 0; i < 4; i++) {
        int r = row0 + i * 16 + ty;
#pragma unroll
        for (int j = 0; j < 8; j++) {
            int n = j * 16 + tx;
            float a = acc1[i][j] + b1[n];
            float g = accg[i][j] + bg[n];
            g = fmaxf(g, 0.f);
            float hv = fmaxf(a * g, 0.f);
            g_h[(size_t)r * Hdim + n] = hv;
        }
    }
}

// ---------------------------------------------------------------------------
// Kernel 2: logits = h @ w2 + b2   (one thread per token row)
// ---------------------------------------------------------------------------
__global__ __launch_bounds__(256) void k_logits(
    const float* __restrict__ w2, const float* __restrict__ b2)
{
    __shared__ float W2s[Hdim * Ecnt];
    const int tid = threadIdx.x;
    for (int i = tid; i < Hdim * Ecnt; i += 256) W2s[i] = w2[i];
    __syncthreads();

    const int b = blockIdx.x * 256 + tid;
    float acc[Ecnt];
#pragma unroll
    for (int e = 0; e < Ecnt; e++) acc[e] = b2[e];
    const float* hr = g_h + (size_t)b * Hdim;
#pragma unroll 4
    for (int k = 0; k < Hdim; k++) {
        float hv = hr[k];
#pragma unroll
        for (int e = 0; e < Ecnt; e++) acc[e] = fmaf(hv, W2s[k * Ecnt + e], acc[e]);
    }
#pragma unroll
    for (int e = 0; e < Ecnt; e++) g_logits[(size_t)b * Ecnt + e] = acc[e];
}

// ---------------------------------------------------------------------------
// Kernel 3: per expert — column softmax over batch, exact top-2048 selection
// (radix bisection on float bits, lowest-index tie-break), renorm softmax.
// One block per expert, 1024 threads.
// ---------------------------------------------------------------------------
__global__ __launch_bounds__(1024) void k_select()
{
    __shared__ float lv[Bsz];      // 32 KB softmax values for this column
    __shared__ float redf[1024];
    __shared__ int   redi[1024];
    __shared__ unsigned s_cnt;
    __shared__ float s_bf;
    __shared__ int   s_bi;

    const int e   = blockIdx.x;
    const int tid = threadIdx.x;

    float loc[8];
#pragma unroll
    for (int r = 0; r < 8; r++) {
        int i = tid + r * 1024;
        loc[r] = g_logits[(size_t)i * Ecnt + e];
        g_sel_slot[i][e] = -1;
    }

    // --- column max ---
    float m = -1e30f;
#pragma unroll
    for (int r = 0; r < 8; r++) m = fmaxf(m, loc[r]);
    redf[tid] = m; __syncthreads();
    for (int s = 512; s > 0; s >>= 1) {
        if (tid < s) redf[tid] = fmaxf(redf[tid], redf[tid + s]);
        __syncthreads();
    }
    if (tid == 0) s_bf = redf[0];
    __syncthreads();
    m = s_bf;
    __syncthreads();

    // --- column sum of exp ---
    float s = 0.f;
#pragma unroll
    for (int r = 0; r < 8; r++) s += expf(loc[r] - m);
    redf[tid] = s; __syncthreads();
    for (int st = 512; st > 0; st >>= 1) {
        if (tid < st) redf[tid] += redf[tid + st];
        __syncthreads();
    }
    if (tid == 0) s_bf = redf[0];
    __syncthreads();
    s = s_bf;
    __syncthreads();

    const float inv_s = 1.0f / s;
#pragma unroll
    for (int r = 0; r < 8; r++) lv[tid + r * 1024] = expf(loc[r] - m) * inv_s;
    __syncthreads();

    // --- radix bisection: V = 2048th largest value (as uint bits; all >= 0) ---
    unsigned cur = 0u;
    for (int bit = 31; bit >= 0; bit--) {
        unsigned cand = cur | (1u << bit);
        int c = 0;
#pragma unroll
        for (int r = 0; r < 8; r++)
            c += (__float_as_uint(lv[tid + r * 1024]) >= cand) ? 1 : 0;
        redi[tid] = c; __syncthreads();
        for (int st = 512; st > 0; st >>= 1) {
            if (tid < st) redi[tid] += redi[tid + st];
            __syncthreads();
        }
        if (tid == 0) s_bi = redi[0];
        __syncthreads();
        if (s_bi >= BKSEL) cur = cand;
        __syncthreads();
    }
    const unsigned V = cur;

    // --- collect strictly-greater first (order irrelevant), then equals by
    //     ascending index (matches jax.lax.top_k tie-break) ---
    if (tid == 0) s_cnt = 0u;
    __syncthreads();
#pragma unroll
    for (int r = 0; r < 8; r++) {
        int i = tid + r * 1024;
        if (__float_as_uint(lv[i]) > V) {
            unsigned p = atomicAdd(&s_cnt, 1u);
            g_idx[e][p] = i;
            g_sel_slot[i][e] = (int)p;
        }
    }
    __syncthreads();
    if (tid == 0) {
        unsigned p = s_cnt;
        for (int i = 0; i < Bsz && p < BKSEL; i++) {
            if (__float_as_uint(lv[i]) == V) {
                g_idx[e][p] = i;
                g_sel_slot[i][e] = (int)p;
                p++;
            }
        }
    }
    __syncthreads();

    // --- nws = softmax over the 2048 selected weights ---
    float wsv[2];
    float m2 = -1e30f;
#pragma unroll
    for (int r = 0; r < 2; r++) {
        int slot = tid + r * 1024;
        wsv[r] = lv[g_idx[e][slot]];
        m2 = fmaxf(m2, wsv[r]);
    }
    redf[tid] = m2; __syncthreads();
    for (int st = 512; st > 0; st >>= 1) {
        if (tid < st) redf[tid] = fmaxf(redf[tid], redf[tid + st]);
        __syncthreads();
    }
    if (tid == 0) s_bf = redf[0];
    __syncthreads();
    m2 = s_bf;
    __syncthreads();

    float s2 = expf(wsv[0] - m2) + expf(wsv[1] - m2);
    redf[tid] = s2; __syncthreads();
    for (int st = 512; st > 0; st >>= 1) {
        if (tid < st) redf[tid] += redf[tid + st];
        __syncthreads();
    }
    if (tid == 0) s_bf = redf[0];
    __syncthreads();
    s2 = s_bf;

    const float inv_s2 = 1.0f / s2;
#pragma unroll
    for (int r = 0; r < 2; r++)
        g_nws[e][tid + r * 1024] = expf(wsv[r] - m2) * inv_s2;
}

// ---------------------------------------------------------------------------
// Kernel 4: expert GEMM with gathered rows:
//   eo[slot, e, :] = (x[idx[e][slot]] @ we[e] + be[e]) * nws[e][slot]
// 128x128 tile / block, 256 threads, 8x8 thread tile, fp32.
// ---------------------------------------------------------------------------
__global__ __launch_bounds__(256) void k_expert(
    const float* __restrict__ x,
    const float* __restrict__ we, const float* __restrict__ be)
{
    __shared__ float As[16][128];
    __shared__ float Bs[16][128];
    __shared__ int   ridx[128];

    const int e  = blockIdx.z;
    const int m0 = blockIdx.y * 128;
    const int n0 = blockIdx.x * 128;
    const int tid = threadIdx.x;
    const int tx  = tid & 15;
    const int ty  = tid >> 4;

    if (tid < 128) ridx[tid] = g_idx[e][m0 + tid];
    __syncthreads();

    float acc[8][8];
#pragma unroll
    for (int i = 0; i < 8; i++)
#pragma unroll
        for (int j = 0; j < 8; j++) acc[i][j] = 0.f;

    const float* weE = we + (size_t)e * DIN * DOUT;

    for (int k0 = 0; k0 < DIN; k0 += 16) {
        // A tile: 128 rows x 16 k = 512 float4, gathered
#pragma unroll
        for (int r = 0; r < 2; r++) {
            int lin = tid + r * 256;
            int mm  = lin >> 2;
            int kq  = (lin & 3) << 2;
            float4 v = *(const float4*)(x + (size_t)ridx[mm] * DIN + k0 + kq);
            As[kq + 0][mm] = v.x; As[kq + 1][mm] = v.y;
            As[kq + 2][mm] = v.z; As[kq + 3][mm] = v.w;
        }
        // B tile: 16 k x 128 n = 512 float4, coalesced
#pragma unroll
        for (int r = 0; r < 2; r++) {
            int lin = tid + r * 256;
            int kk  = lin >> 5;
            int nq  = (lin & 31) << 2;
            *(float4*)&Bs[kk][nq] =
                *(const float4*)(weE + (size_t)(k0 + kk) * DOUT + n0 + nq);
        }
        __syncthreads();
#pragma unroll
        for (int kk = 0; kk < 16; kk++) {
            float ar[8], br[8];
#pragma unroll
            for (int i = 0; i < 8; i++) ar[i] = As[kk][i * 16 + ty];
#pragma unroll
            for (int j = 0; j < 8; j++) br[j] = Bs[kk][j * 16 + tx];
#pragma unroll
            for (int i = 0; i < 8; i++)
#pragma unroll
                for (int j = 0; j < 8; j++)
                    acc[i][j] = fmaf(ar[i], br[j], acc[i][j]);
        }
        __syncthreads();
    }

#pragma unroll
    for (int i = 0; i < 8; i++) {
        int slot = m0 + i * 16 + ty;
        float nw = g_nws[e][slot];
        float* orow = g_eo + ((size_t)slot * Ecnt + e) * DOUT + n0;
#pragma unroll
        for (int j = 0; j < 8; j++) {
            int n = j * 16 + tx;
            orow[n] = (acc[i][j] + be[(size_t)e * DOUT + n0 + n]) * nw;
        }
    }
}

// ---------------------------------------------------------------------------
// Kernel 5: combine. For token row b:
//   c_e = eo[slot(b,e), e, :] if selected else 0
//   out[b, e*DOUT + d] = c_e[d] + sum_e' c_e'[d]
// No atomics needed: temp_sum is exactly the per-row sum over experts.
// ---------------------------------------------------------------------------
__global__ __launch_bounds__(256) void k_combine(float* __restrict__ out)
{
    __shared__ int slots[Ecnt];
    const int b   = blockIdx.x;
    const int tid = threadIdx.x;
    if (tid < Ecnt) slots[tid] = g_sel_slot[b][tid];
    __syncthreads();

#pragma unroll
    for (int r = 0; r < 4; r++) {
        int d = tid + r * 256;
        float c[Ecnt];
        float ssum = 0.f;
#pragma unroll
        for (int e = 0; e < Ecnt; e++) {
            int slot = slots[e];
            float v = 0.f;
            if (slot >= 0) v = g_eo[((size_t)slot * Ecnt + e) * DOUT + d];
            c[e] = v;
            ssum += v;
        }
        float* orow = out + (size_t)b * (Ecnt * DOUT) + d;
#pragma unroll
        for (int e = 0; e < Ecnt; e++)
            orow[(size_t)e * DOUT] = c[e] + ssum;
    }
}

// ---------------------------------------------------------------------------
extern "C" void kernel_launch(void* const* d_in, const int* in_sizes, int n_in,
                              void* d_out, int out_size)
{
    const float* x  = (const float*)d_in[0];
    const float* w1 = (const float*)d_in[1];
    const float* b1 = (const float*)d_in[2];
    const float* wg = (const float*)d_in[3];
    const float* bg = (const float*)d_in[4];
    const float* w2 = (const float*)d_in[5];
    const float* b2 = (const float*)d_in[6];
    const float* we = (const float*)d_in[7];
    const float* be = (const float*)d_in[8];
    float* out = (float*)d_out;

    k_router<<<Bsz / 64, 256>>>(x, w1, b1, wg, bg);
    k_logits<<<Bsz / 256, 256>>>(w2, b2);
    k_select<<<Ecnt, 1024>>>();
    k_expert<<<dim3(DOUT / 128, BKSEL / 128, Ecnt), 256>>>(x, we, be);
    k_combine<<<Bsz, 256>>>(out);
}

// round 3
// speedup vs baseline: 1.0010x; 1.0010x over previous
#include <cuda_runtime.h>
#include <math.h>
#include <stdint.h>

#define Bsz   8192
#define DIN   1024
#define Hdim  128
#define Ecnt  8
#define DOUT  1024
#define BKSEL 2048   // ceil(K*B/E) = ceil(2*8192/8)

// ---------------- scratch (device globals; no runtime allocation) ----------
__device__ float g_h[Bsz * Hdim];            // 4 MB  router hidden
__device__ float g_logits[Bsz * Ecnt];       // 256 KB
__device__ int   g_idx[Ecnt][BKSEL];         // selected token index per (e, slot)
__device__ float g_nws[Ecnt][BKSEL];         // renormalized weights
__device__ int   g_sel_slot[Bsz][Ecnt];      // token,expert -> slot or -1
__device__ float g_eo[(size_t)BKSEL * Ecnt * DOUT]; // 64 MB  [slot][e][d]

// ---------------------------------------------------------------------------
// Kernel 1: router hidden h = relu((x@w1+b1) * relu(x@wg+bg))
// 64-row x 128-col tile per block, 256 threads, thread tile 4x8 per matrix.
// ---------------------------------------------------------------------------
__global__ __launch_bounds__(256) void k_router(
    const float* __restrict__ x,
    const float* __restrict__ w1, const float* __restrict__ b1,
    const float* __restrict__ wg, const float* __restrict__ bg)
{
    __shared__ float Xs[16][64];
    __shared__ float W1s[16][128];
    __shared__ float WGs[16][128];

    const int tid = threadIdx.x;
    const int tx  = tid & 15;     // col lane
    const int ty  = tid >> 4;     // row lane
    const int row0 = blockIdx.x * 64;

    float acc1[4][8];
    float accg[4][8];
#pragma unroll
    for (int i = 0; i < 4; i++)
#pragma unroll
        for (int j = 0; j < 8; j++) { acc1[i][j] = 0.f; accg[i][j] = 0.f; }

    for (int k0 = 0; k0 < DIN; k0 += 16) {
        // X tile: 64 rows x 16 k = 1024 floats -> 256 threads x 1 float4
        {
            int lin = tid;
            int m  = lin >> 2;
            int kq = (lin & 3) << 2;
            float4 v = *(const float4*)(x + (size_t)(row0 + m) * DIN + k0 + kq);
            Xs[kq + 0][m] = v.x; Xs[kq + 1][m] = v.y;
            Xs[kq + 2][m] = v.z; Xs[kq + 3][m] = v.w;
        }
        // W tiles: 16 x 128 each = 512 float4 -> 2 per thread
#pragma unroll
        for (int r = 0; r < 2; r++) {
            int lin = tid + r * 256;
            int kk  = lin >> 5;
            int nq  = (lin & 31) << 2;
            *(float4*)&W1s[kk][nq] = *(const float4*)(w1 + (size_t)(k0 + kk) * Hdim + nq);
            *(float4*)&WGs[kk][nq] = *(const float4*)(wg + (size_t)(k0 + kk) * Hdim + nq);
        }
        __syncthreads();
#pragma unroll
        for (int kk = 0; kk < 16; kk++) {
            float xr[4], w1r[8], wgr[8];
#pragma unroll
            for (int i = 0; i < 4; i++) xr[i] = Xs[kk][i * 16 + ty];
#pragma unroll
            for (int j = 0; j < 8; j++) {
                w1r[j] = W1s[kk][j * 16 + tx];
                wgr[j] = WGs[kk][j * 16 + tx];
            }
#pragma unroll
            for (int i = 0; i < 4; i++)
#pragma unroll
                for (int j = 0; j < 8; j++) {
                    acc1[i][j] = fmaf(xr[i], w1r[j], acc1[i][j]);
                    accg[i][j] = fmaf(xr[i], wgr[j], accg[i][j]);
                }
        }
        __syncthreads();
    }
#pragma unroll
    for (int i = 0; i < 4; i++) {
        int r = row0 + i * 16 + ty;
#pragma unroll
        for (int j = 0; j < 8; j++) {
            int n = j * 16 + tx;
            float a = acc1[i][j] + b1[n];
            float g = accg[i][j] + bg[n];
            g = fmaxf(g, 0.f);
            float hv = fmaxf(a * g, 0.f);
            g_h[(size_t)r * Hdim + n] = hv;
        }
    }
}

// ---------------------------------------------------------------------------
// Kernel 2: logits = h @ w2 + b2   (one thread per token row)
// ---------------------------------------------------------------------------
__global__ __launch_bounds__(256) void k_logits(
    const float* __restrict__ w2, const float* __restrict__ b2)
{
    __shared__ float W2s[Hdim * Ecnt];
    const int tid = threadIdx.x;
    for (int i = tid; i < Hdim * Ecnt; i += 256) W2s[i] = w2[i];
    __syncthreads();

    const int b = blockIdx.x * 256 + tid;
    float acc[Ecnt];
#pragma unroll
    for (int e = 0; e < Ecnt; e++) acc[e] = b2[e];
    const float* hr = g_h + (size_t)b * Hdim;
#pragma unroll 4
    for (int k = 0; k < Hdim; k++) {
        float hv = hr[k];
#pragma unroll
        for (int e = 0; e < Ecnt; e++) acc[e] = fmaf(hv, W2s[k * Ecnt + e], acc[e]);
    }
#pragma unroll
    for (int e = 0; e < Ecnt; e++) g_logits[(size_t)b * Ecnt + e] = acc[e];
}

// ---------------------------------------------------------------------------
// Kernel 3: per expert — column softmax over batch, exact top-2048 selection
// (radix bisection on float bits, lowest-index tie-break), renorm softmax.
// One block per expert, 1024 threads.
// ---------------------------------------------------------------------------
__global__ __launch_bounds__(1024) void k_select()
{
    __shared__ float lv[Bsz];      // 32 KB softmax values for this column
    __shared__ float redf[1024];
    __shared__ int   redi[1024];
    __shared__ unsigned s_cnt;
    __shared__ float s_bf;
    __shared__ int   s_bi;

    const int e   = blockIdx.x;
    const int tid = threadIdx.x;

    float loc[8];
#pragma unroll
    for (int r = 0; r < 8; r++) {
        int i = tid + r * 1024;
        loc[r] = g_logits[(size_t)i * Ecnt + e];
        g_sel_slot[i][e] = -1;
    }

    // --- column max ---
    float m = -1e30f;
#pragma unroll
    for (int r = 0; r < 8; r++) m = fmaxf(m, loc[r]);
    redf[tid] = m; __syncthreads();
    for (int s = 512; s > 0; s >>= 1) {
        if (tid < s) redf[tid] = fmaxf(redf[tid], redf[tid + s]);
        __syncthreads();
    }
    if (tid == 0) s_bf = redf[0];
    __syncthreads();
    m = s_bf;
    __syncthreads();

    // --- column sum of exp ---
    float s = 0.f;
#pragma unroll
    for (int r = 0; r < 8; r++) s += expf(loc[r] - m);
    redf[tid] = s; __syncthreads();
    for (int st = 512; st > 0; st >>= 1) {
        if (tid < st) redf[tid] += redf[tid + st];
        __syncthreads();
    }
    if (tid == 0) s_bf = redf[0];
    __syncthreads();
    s = s_bf;
    __syncthreads();

    const float inv_s = 1.0f / s;
#pragma unroll
    for (int r = 0; r < 8; r++) lv[tid + r * 1024] = expf(loc[r] - m) * inv_s;
    __syncthreads();

    // --- radix bisection: V = 2048th largest value (as uint bits; all >= 0) ---
    unsigned cur = 0u;
    for (int bit = 31; bit >= 0; bit--) {
        unsigned cand = cur | (1u << bit);
        int c = 0;
#pragma unroll
        for (int r = 0; r < 8; r++)
            c += (__float_as_uint(lv[tid + r * 1024]) >= cand) ? 1 : 0;
        redi[tid] = c; __syncthreads();
        for (int st = 512; st > 0; st >>= 1) {
            if (tid < st) redi[tid] += redi[tid + st];
            __syncthreads();
        }
        if (tid == 0) s_bi = redi[0];
        __syncthreads();
        if (s_bi >= BKSEL) cur = cand;
        __syncthreads();
    }
    const unsigned V = cur;

    // --- collect strictly-greater first (order irrelevant), then equals by
    //     ascending index (matches jax.lax.top_k tie-break) ---
    if (tid == 0) s_cnt = 0u;
    __syncthreads();
#pragma unroll
    for (int r = 0; r < 8; r++) {
        int i = tid + r * 1024;
        if (__float_as_uint(lv[i]) > V) {
            unsigned p = atomicAdd(&s_cnt, 1u);
            g_idx[e][p] = i;
            g_sel_slot[i][e] = (int)p;
        }
    }
    __syncthreads();
    if (tid == 0) {
        unsigned p = s_cnt;
        for (int i = 0; i < Bsz && p < BKSEL; i++) {
            if (__float_as_uint(lv[i]) == V) {
                g_idx[e][p] = i;
                g_sel_slot[i][e] = (int)p;
                p++;
            }
        }
    }
    __syncthreads();

    // --- nws = softmax over the 2048 selected weights ---
    float wsv[2];
    float m2 = -1e30f;
#pragma unroll
    for (int r = 0; r < 2; r++) {
        int slot = tid + r * 1024;
        wsv[r] = lv[g_idx[e][slot]];
        m2 = fmaxf(m2, wsv[r]);
    }
    redf[tid] = m2; __syncthreads();
    for (int st = 512; st > 0; st >>= 1) {
        if (tid < st) redf[tid] = fmaxf(redf[tid], redf[tid + st]);
        __syncthreads();
    }
    if (tid == 0) s_bf = redf[0];
    __syncthreads();
    m2 = s_bf;
    __syncthreads();

    float s2 = expf(wsv[0] - m2) + expf(wsv[1] - m2);
    redf[tid] = s2; __syncthreads();
    for (int st = 512; st > 0; st >>= 1) {
        if (tid < st) redf[tid] += redf[tid + st];
        __syncthreads();
    }
    if (tid == 0) s_bf = redf[0];
    __syncthreads();
    s2 = s_bf;

    const float inv_s2 = 1.0f / s2;
#pragma unroll
    for (int r = 0; r < 2; r++)
        g_nws[e][tid + r * 1024] = expf(wsv[r] - m2) * inv_s2;
}

// ---------------------------------------------------------------------------
// Kernel 4: expert GEMM with gathered rows:
//   eo[slot, e, :] = (x[idx[e][slot]] @ we[e] + be[e]) * nws[e][slot]
// 128x128 tile / block, 256 threads, 8x8 thread tile, fp32.
// ---------------------------------------------------------------------------
__global__ __launch_bounds__(256) void k_expert(
    const float* __restrict__ x,
    const float* __restrict__ we, const float* __restrict__ be)
{
    __shared__ float As[16][128];
    __shared__ float Bs[16][128];
    __shared__ int   ridx[128];

    const int e  = blockIdx.z;
    const int m0 = blockIdx.y * 128;
    const int n0 = blockIdx.x * 128;
    const int tid = threadIdx.x;
    const int tx  = tid & 15;
    const int ty  = tid >> 4;

    if (tid < 128) ridx[tid] = g_idx[e][m0 + tid];
    __syncthreads();

    float acc[8][8];
#pragma unroll
    for (int i = 0; i < 8; i++)
#pragma unroll
        for (int j = 0; j < 8; j++) acc[i][j] = 0.f;

    const float* weE = we + (size_t)e * DIN * DOUT;

    for (int k0 = 0; k0 < DIN; k0 += 16) {
        // A tile: 128 rows x 16 k = 512 float4, gathered
#pragma unroll
        for (int r = 0; r < 2; r++) {
            int lin = tid + r * 256;
            int mm  = lin >> 2;
            int kq  = (lin & 3) << 2;
            float4 v = *(const float4*)(x + (size_t)ridx[mm] * DIN + k0 + kq);
            As[kq + 0][mm] = v.x; As[kq + 1][mm] = v.y;
            As[kq + 2][mm] = v.z; As[kq + 3][mm] = v.w;
        }
        // B tile: 16 k x 128 n = 512 float4, coalesced
#pragma unroll
        for (int r = 0; r < 2; r++) {
            int lin = tid + r * 256;
            int kk  = lin >> 5;
            int nq  = (lin & 31) << 2;
            *(float4*)&Bs[kk][nq] =
                *(const float4*)(weE + (size_t)(k0 + kk) * DOUT + n0 + nq);
        }
        __syncthreads();
#pragma unroll
        for (int kk = 0; kk < 16; kk++) {
            float ar[8], br[8];
#pragma unroll
            for (int i = 0; i < 8; i++) ar[i] = As[kk][i * 16 + ty];
#pragma unroll
            for (int j = 0; j < 8; j++) br[j] = Bs[kk][j * 16 + tx];
#pragma unroll
            for (int i = 0; i < 8; i++)
#pragma unroll
                for (int j = 0; j < 8; j++)
                    acc[i][j] = fmaf(ar[i], br[j], acc[i][j]);
        }
        __syncthreads();
    }

#pragma unroll
    for (int i = 0; i < 8; i++) {
        int slot = m0 + i * 16 + ty;
        float nw = g_nws[e][slot];
        float* orow = g_eo + ((size_t)slot * Ecnt + e) * DOUT + n0;
#pragma unroll
        for (int j = 0; j < 8; j++) {
            int n = j * 16 + tx;
            orow[n] = (acc[i][j] + be[(size_t)e * DOUT + n0 + n]) * nw;
        }
    }
}

// ---------------------------------------------------------------------------
// Kernel 5: combine. For token row b:
//   c_e = eo[slot(b,e), e, :] if selected else 0
//   out[b, e*DOUT + d] = c_e[d] + sum_e' c_e'[d]
// No atomics needed: temp_sum is exactly the per-row sum over experts.
// ---------------------------------------------------------------------------
__global__ __launch_bounds__(256) void k_combine(float* __restrict__ out)
{
    __shared__ int slots[Ecnt];
    const int b   = blockIdx.x;
    const int tid = threadIdx.x;
    if (tid < Ecnt) slots[tid] = g_sel_slot[b][tid];
    __syncthreads();

#pragma unroll
    for (int r = 0; r < 4; r++) {
        int d = tid + r * 256;
        float c[Ecnt];
        float ssum = 0.f;
#pragma unroll
        for (int e = 0; e < Ecnt; e++) {
            int slot = slots[e];
            float v = 0.f;
            if (slot >= 0) v = g_eo[((size_t)slot * Ecnt + e) * DOUT + d];
            c[e] = v;
            ssum += v;
        }
        float* orow = out + (size_t)b * (Ecnt * DOUT) + d;
#pragma unroll
        for (int e = 0; e < Ecnt; e++)
            orow[(size_t)e * DOUT] = c[e] + ssum;
    }
}

// ---------------------------------------------------------------------------
extern "C" void kernel_launch(void* const* d_in, const int* in_sizes, int n_in,
                              void* d_out, int out_size)
{
    const float* x  = (const float*)d_in[0];
    const float* w1 = (const float*)d_in[1];
    const float* b1 = (const float*)d_in[2];
    const float* wg = (const float*)d_in[3];
    const float* bg = (const float*)d_in[4];
    const float* w2 = (const float*)d_in[5];
    const float* b2 = (const float*)d_in[6];
    const float* we = (const float*)d_in[7];
    const float* be = (const float*)d_in[8];
    float* out = (float*)d_out;

    k_router<<<Bsz / 64, 256>>>(x, w1, b1, wg, bg);
    k_logits<<<Bsz / 256, 256>>>(w2, b2);
    k_select<<<Ecnt, 1024>>>();
    k_expert<<<dim3(DOUT / 128, BKSEL / 128, Ecnt), 256>>>(x, we, be);
    k_combine<<<Bsz, 256>>>(out);
}

// round 5
// speedup vs baseline: 1.8146x; 1.8128x over previous
#include <cuda_runtime.h>
#include <math.h>
#include <stdint.h>

#define Bsz   8192
#define DIN   1024
#define Hdim  128
#define Ecnt  8
#define DOUT  1024
#define BKSEL 2048   // ceil(K*B/E) = ceil(2*8192/8)

// ---------------- scratch (device globals; no runtime allocation) ----------
__device__ float g_h[Bsz * Hdim];            // 4 MB  router hidden
__device__ float g_logits[Bsz * Ecnt];       // 256 KB
__device__ int   g_idx[Ecnt][BKSEL];         // selected token index per (e, slot)
__device__ float g_nws[Ecnt][BKSEL];         // renormalized weights
__device__ int   g_sel_slot[Bsz][Ecnt];      // token,expert -> slot or -1
__device__ float g_eo[(size_t)BKSEL * Ecnt * DOUT]; // 64 MB  [slot][e][d]

// ---------------------------------------------------------------------------
// helpers
// ---------------------------------------------------------------------------
__device__ __forceinline__ void cp_async16(void* smem, const void* gmem) {
    uint32_t s = (uint32_t)__cvta_generic_to_shared(smem);
    asm volatile("cp.async.cg.shared.global [%0], [%1], 16;\n" :: "r"(s), "l"(gmem));
}
__device__ __forceinline__ uint32_t f2tf32(float v) {
    uint32_t r;
    asm("cvt.rna.tf32.f32 %0, %1;\n" : "=r"(r) : "f"(v));
    return r;
}
__device__ __forceinline__ void mma_tf32(float* cc,
                                         const uint32_t* a, const uint32_t* b) {
    asm volatile(
        "mma.sync.aligned.m16n8k8.row.col.f32.tf32.tf32.f32 "
        "{%0,%1,%2,%3}, {%4,%5,%6,%7}, {%8,%9}, {%0,%1,%2,%3};\n"
        : "+f"(cc[0]), "+f"(cc[1]), "+f"(cc[2]), "+f"(cc[3])
        : "r"(a[0]), "r"(a[1]), "r"(a[2]), "r"(a[3]), "r"(b[0]), "r"(b[1]));
}

// ---------------------------------------------------------------------------
// Kernel 1: router hidden h = relu((x@w1+b1) * relu(x@wg+bg))  — full fp32,
// selection-critical, unchanged.
// ---------------------------------------------------------------------------
__global__ __launch_bounds__(256) void k_router(
    const float* __restrict__ x,
    const float* __restrict__ w1, const float* __restrict__ b1,
    const float* __restrict__ wg, const float* __restrict__ bg)
{
    __shared__ float Xs[16][64];
    __shared__ float W1s[16][128];
    __shared__ float WGs[16][128];

    const int tid = threadIdx.x;
    const int tx  = tid & 15;
    const int ty  = tid >> 4;
    const int row0 = blockIdx.x * 64;

    float acc1[4][8];
    float accg[4][8];
#pragma unroll
    for (int i = 0; i < 4; i++)
#pragma unroll
        for (int j = 0; j < 8; j++) { acc1[i][j] = 0.f; accg[i][j] = 0.f; }

    for (int k0 = 0; k0 < DIN; k0 += 16) {
        {
            int lin = tid;
            int m  = lin >> 2;
            int kq = (lin & 3) << 2;
            float4 v = *(const float4*)(x + (size_t)(row0 + m) * DIN + k0 + kq);
            Xs[kq + 0][m] = v.x; Xs[kq + 1][m] = v.y;
            Xs[kq + 2][m] = v.z; Xs[kq + 3][m] = v.w;
        }
#pragma unroll
        for (int r = 0; r < 2; r++) {
            int lin = tid + r * 256;
            int kk  = lin >> 5;
            int nq  = (lin & 31) << 2;
            *(float4*)&W1s[kk][nq] = *(const float4*)(w1 + (size_t)(k0 + kk) * Hdim + nq);
            *(float4*)&WGs[kk][nq] = *(const float4*)(wg + (size_t)(k0 + kk) * Hdim + nq);
        }
        __syncthreads();
#pragma unroll
        for (int kk = 0; kk < 16; kk++) {
            float xr[4], w1r[8], wgr[8];
#pragma unroll
            for (int i = 0; i < 4; i++) xr[i] = Xs[kk][i * 16 + ty];
#pragma unroll
            for (int j = 0; j < 8; j++) {
                w1r[j] = W1s[kk][j * 16 + tx];
                wgr[j] = WGs[kk][j * 16 + tx];
            }
#pragma unroll
            for (int i = 0; i < 4; i++)
#pragma unroll
                for (int j = 0; j < 8; j++) {
                    acc1[i][j] = fmaf(xr[i], w1r[j], acc1[i][j]);
                    accg[i][j] = fmaf(xr[i], wgr[j], accg[i][j]);
                }
        }
        __syncthreads();
    }
#pragma unroll
    for (int i = 0; i < 4; i++) {
        int r = row0 + i * 16 + ty;
#pragma unroll
        for (int j = 0; j < 8; j++) {
            int n = j * 16 + tx;
            float a = acc1[i][j] + b1[n];
            float g = accg[i][j] + bg[n];
            g = fmaxf(g, 0.f);
            float hv = fmaxf(a * g, 0.f);
            g_h[(size_t)r * Hdim + n] = hv;
        }
    }
}

// ---------------------------------------------------------------------------
// Kernel 2: logits = h @ w2 + b2   (one thread per token row)
// ---------------------------------------------------------------------------
__global__ __launch_bounds__(256) void k_logits(
    const float* __restrict__ w2, const float* __restrict__ b2)
{
    __shared__ float W2s[Hdim * Ecnt];
    const int tid = threadIdx.x;
    for (int i = tid; i < Hdim * Ecnt; i += 256) W2s[i] = w2[i];
    __syncthreads();

    const int b = blockIdx.x * 256 + tid;
    float acc[Ecnt];
#pragma unroll
    for (int e = 0; e < Ecnt; e++) acc[e] = b2[e];
    const float* hr = g_h + (size_t)b * Hdim;
#pragma unroll 4
    for (int k = 0; k < Hdim; k++) {
        float hv = hr[k];
#pragma unroll
        for (int e = 0; e < Ecnt; e++) acc[e] = fmaf(hv, W2s[k * Ecnt + e], acc[e]);
    }
#pragma unroll
    for (int e = 0; e < Ecnt; e++) g_logits[(size_t)b * Ecnt + e] = acc[e];
}

// ---------------------------------------------------------------------------
// Kernel 3: per expert — column softmax over batch, exact top-2048 selection.
// Bisection counts now use warp shuffle + shared atomic: 1 sync per bit.
// ---------------------------------------------------------------------------
__global__ __launch_bounds__(1024) void k_select()
{
    __shared__ float lv[Bsz];      // 32 KB softmax values for this column
    __shared__ float redf[1024];
    __shared__ int   s_bits[32];   // per-bit bisection counters
    __shared__ unsigned s_cnt;
    __shared__ float s_bf;

    const int e   = blockIdx.x;
    const int tid = threadIdx.x;

    float loc[8];
#pragma unroll
    for (int r = 0; r < 8; r++) {
        int i = tid + r * 1024;
        loc[r] = g_logits[(size_t)i * Ecnt + e];
        g_sel_slot[i][e] = -1;
    }
    if (tid < 32) s_bits[tid] = 0;

    // --- column max ---
    float m = -1e30f;
#pragma unroll
    for (int r = 0; r < 8; r++) m = fmaxf(m, loc[r]);
    redf[tid] = m; __syncthreads();
    for (int s = 512; s > 0; s >>= 1) {
        if (tid < s) redf[tid] = fmaxf(redf[tid], redf[tid + s]);
        __syncthreads();
    }
    if (tid == 0) s_bf = redf[0];
    __syncthreads();
    m = s_bf;
    __syncthreads();

    // --- column sum of exp ---
    float s = 0.f;
#pragma unroll
    for (int r = 0; r < 8; r++) s += expf(loc[r] - m);
    redf[tid] = s; __syncthreads();
    for (int st = 512; st > 0; st >>= 1) {
        if (tid < st) redf[tid] += redf[tid + st];
        __syncthreads();
    }
    if (tid == 0) s_bf = redf[0];
    __syncthreads();
    s = s_bf;
    __syncthreads();

    const float inv_s = 1.0f / s;
    unsigned ub[8];
#pragma unroll
    for (int r = 0; r < 8; r++) {
        float v = expf(loc[r] - m) * inv_s;
        lv[tid + r * 1024] = v;
        ub[r] = __float_as_uint(v);
    }
    __syncthreads();

    // --- radix bisection: V = 2048th largest value (uint bits; all >= 0) ---
    unsigned cur = 0u;
    for (int bit = 31; bit >= 0; bit--) {
        unsigned cand = cur | (1u << bit);
        int c = 0;
#pragma unroll
        for (int r = 0; r < 8; r++) c += (ub[r] >= cand) ? 1 : 0;
#pragma unroll
        for (int o = 16; o > 0; o >>= 1) c += __shfl_xor_sync(0xffffffffu, c, o);
        if ((tid & 31) == 0) atomicAdd(&s_bits[bit], c);
        __syncthreads();
        if (s_bits[bit] >= BKSEL) cur = cand;
    }
    const unsigned V = cur;

    // --- collect strictly-greater first (order irrelevant), then equals by
    //     ascending index (matches jax.lax.top_k tie-break) ---
    if (tid == 0) s_cnt = 0u;
    __syncthreads();
#pragma unroll
    for (int r = 0; r < 8; r++) {
        int i = tid + r * 1024;
        if (ub[r] > V) {
            unsigned p = atomicAdd(&s_cnt, 1u);
            g_idx[e][p] = i;
            g_sel_slot[i][e] = (int)p;
        }
    }
    __syncthreads();
    if (tid == 0) {
        unsigned p = s_cnt;
        for (int i = 0; i < Bsz && p < BKSEL; i++) {
            if (__float_as_uint(lv[i]) == V) {
                g_idx[e][p] = i;
                g_sel_slot[i][e] = (int)p;
                p++;
            }
        }
    }
    __syncthreads();

    // --- nws = softmax over the 2048 selected weights ---
    float wsv[2];
    float m2 = -1e30f;
#pragma unroll
    for (int r = 0; r < 2; r++) {
        int slot = tid + r * 1024;
        wsv[r] = lv[g_idx[e][slot]];
        m2 = fmaxf(m2, wsv[r]);
    }
    redf[tid] = m2; __syncthreads();
    for (int st = 512; st > 0; st >>= 1) {
        if (tid < st) redf[tid] = fmaxf(redf[tid], redf[tid + st]);
        __syncthreads();
    }
    if (tid == 0) s_bf = redf[0];
    __syncthreads();
    m2 = s_bf;
    __syncthreads();

    float s2 = expf(wsv[0] - m2) + expf(wsv[1] - m2);
    redf[tid] = s2; __syncthreads();
    for (int st = 512; st > 0; st >>= 1) {
        if (tid < st) redf[tid] += redf[tid + st];
        __syncthreads();
    }
    if (tid == 0) s_bf = redf[0];
    __syncthreads();
    s2 = s_bf;

    const float inv_s2 = 1.0f / s2;
#pragma unroll
    for (int r = 0; r < 2; r++)
        g_nws[e][tid + r * 1024] = expf(wsv[r] - m2) * inv_s2;
}

// ---------------------------------------------------------------------------
// Kernel 4: expert GEMM on tensor cores (tf32 mma.sync m16n8k8):
//   eo[slot, e, :] = (x[idx[e][slot]] @ we[e] + be[e]) * nws[e][slot]
// 128x128 block tile, kb=16, 2-stage cp.async pipeline, 8 warps (2m x 4n),
// warp tile 64x32 = 4x4 mma subtiles. Conflict-free padded smem.
// ---------------------------------------------------------------------------
__global__ __launch_bounds__(256, 2) void k_expert(
    const float* __restrict__ x,
    const float* __restrict__ we, const float* __restrict__ be)
{
    __shared__ float As[2][128][20];   // A: [m][k], stride 20 -> conflict-free frags
    __shared__ float Bs[2][16][136];   // B: [k][n], stride 136 -> conflict-free frags
    __shared__ int   ridx[128];

    const int e  = blockIdx.z;
    const int m0 = blockIdx.y * 128;
    const int n0 = blockIdx.x * 128;
    const int tid  = threadIdx.x;
    const int lane = tid & 31;
    const int w    = tid >> 5;
    const int wm   = w & 1;        // warp row (0..1) -> 64 rows
    const int wn   = w >> 1;       // warp col (0..3) -> 32 cols
    const int g    = lane >> 2;    // group id 0..7
    const int c    = lane & 3;     // thread-in-group 0..3

    if (tid < 128) ridx[tid] = g_idx[e][m0 + tid];
    __syncthreads();

    const float* weE = we + (size_t)e * DIN * DOUT + n0;

    float acc[4][4][4];
#pragma unroll
    for (int mi = 0; mi < 4; mi++)
#pragma unroll
        for (int nj = 0; nj < 4; nj++)
#pragma unroll
            for (int q = 0; q < 4; q++) acc[mi][nj][q] = 0.f;

    // stage loader: A 128x16 (512 f4), B 16x128 (512 f4) -> 4 cp.async / thread
#define LOAD_STAGE(buf, k0)                                                    \
    do {                                                                       \
        _Pragma("unroll")                                                      \
        for (int s_ = 0; s_ < 2; s_++) {                                       \
            int lin = tid + s_ * 256;                                          \
            int row = lin >> 2, col = (lin & 3) << 2;                          \
            cp_async16(&As[buf][row][col],                                     \
                       x + (size_t)ridx[row] * DIN + (k0) + col);              \
        }                                                                      \
        _Pragma("unroll")                                                      \
        for (int s_ = 0; s_ < 2; s_++) {                                       \
            int lin = tid + s_ * 256;                                          \
            int kk_ = lin >> 5, col = (lin & 31) << 2;                         \
            cp_async16(&Bs[buf][kk_][col],                                     \
                       weE + (size_t)((k0) + kk_) * DOUT + col);               \
        }                                                                      \
        asm volatile("cp.async.commit_group;\n");                              \
    } while (0)

    LOAD_STAGE(0, 0);

    const int NT = DIN / 16;   // 64 iterations
    for (int t = 0; t < NT; t++) {
        int buf = t & 1;
        if (t + 1 < NT) {
            LOAD_STAGE(buf ^ 1, (t + 1) * 16);
            asm volatile("cp.async.wait_group 1;\n");
        } else {
            asm volatile("cp.async.wait_group 0;\n");
        }
        __syncthreads();

#pragma unroll
        for (int kk = 0; kk < 2; kk++) {        // two k8 steps per kb=16
            uint32_t aF[4][4];
            uint32_t bF[4][2];
            const int kb8 = kk * 8;
#pragma unroll
            for (int mi = 0; mi < 4; mi++) {
                int row = wm * 64 + mi * 16 + g;
                aF[mi][0] = f2tf32(As[buf][row    ][kb8 + c    ]);
                aF[mi][1] = f2tf32(As[buf][row + 8][kb8 + c    ]);
                aF[mi][2] = f2tf32(As[buf][row    ][kb8 + c + 4]);
                aF[mi][3] = f2tf32(As[buf][row + 8][kb8 + c + 4]);
            }
#pragma unroll
            for (int nj = 0; nj < 4; nj++) {
                int nn = wn * 32 + nj * 8 + g;
                bF[nj][0] = f2tf32(Bs[buf][kb8 + c    ][nn]);
                bF[nj][1] = f2tf32(Bs[buf][kb8 + c + 4][nn]);
            }
#pragma unroll
            for (int mi = 0; mi < 4; mi++)
#pragma unroll
                for (int nj = 0; nj < 4; nj++)
                    mma_tf32(acc[mi][nj], aF[mi], bF[nj]);
        }
        __syncthreads();
    }
#undef LOAD_STAGE

    const float* beE = be + (size_t)e * DOUT + n0;
#pragma unroll
    for (int mi = 0; mi < 4; mi++) {
        int slot0 = m0 + wm * 64 + mi * 16 + g;
        int slot1 = slot0 + 8;
        float nw0 = g_nws[e][slot0];
        float nw1 = g_nws[e][slot1];
        float* o0 = g_eo + ((size_t)slot0 * Ecnt + e) * DOUT + n0;
        float* o1 = g_eo + ((size_t)slot1 * Ecnt + e) * DOUT + n0;
#pragma unroll
        for (int nj = 0; nj < 4; nj++) {
            int n = wn * 32 + nj * 8 + c * 2;
            float bb0 = beE[n], bb1 = beE[n + 1];
            float2 v0, v1;
            v0.x = (acc[mi][nj][0] + bb0) * nw0;
            v0.y = (acc[mi][nj][1] + bb1) * nw0;
            v1.x = (acc[mi][nj][2] + bb0) * nw1;
            v1.y = (acc[mi][nj][3] + bb1) * nw1;
            *(float2*)(o0 + n) = v0;
            *(float2*)(o1 + n) = v1;
        }
    }
}

// ---------------------------------------------------------------------------
// Kernel 5: combine. For token row b:
//   out[b, e*DOUT + d] = c_e[d] + sum_e' c_e'[d]   (no atomics needed)
// ---------------------------------------------------------------------------
__global__ __launch_bounds__(256) void k_combine(float* __restrict__ out)
{
    __shared__ int slots[Ecnt];
    const int b   = blockIdx.x;
    const int tid = threadIdx.x;
    if (tid < Ecnt) slots[tid] = g_sel_slot[b][tid];
    __syncthreads();

#pragma unroll
    for (int r = 0; r < 4; r++) {
        int d = tid + r * 256;
        float cv[Ecnt];
        float ssum = 0.f;
#pragma unroll
        for (int e = 0; e < Ecnt; e++) {
            int slot = slots[e];
            float v = 0.f;
            if (slot >= 0) v = g_eo[((size_t)slot * Ecnt + e) * DOUT + d];
            cv[e] = v;
            ssum += v;
        }
        float* orow = out + (size_t)b * (Ecnt * DOUT) + d;
#pragma unroll
        for (int e = 0; e < Ecnt; e++)
            orow[(size_t)e * DOUT] = cv[e] + ssum;
    }
}

// ---------------------------------------------------------------------------
extern "C" void kernel_launch(void* const* d_in, const int* in_sizes, int n_in,
                              void* d_out, int out_size)
{
    const float* x  = (const float*)d_in[0];
    const float* w1 = (const float*)d_in[1];
    const float* b1 = (const float*)d_in[2];
    const float* wg = (const float*)d_in[3];
    const float* bg = (const float*)d_in[4];
    const float* w2 = (const float*)d_in[5];
    const float* b2 = (const float*)d_in[6];
    const float* we = (const float*)d_in[7];
    const float* be = (const float*)d_in[8];
    float* out = (float*)d_out;

    k_router<<<Bsz / 64, 256>>>(x, w1, b1, wg, bg);
    k_logits<<<Bsz / 256, 256>>>(w2, b2);
    k_select<<<Ecnt, 1024>>>();
    k_expert<<<dim3(DOUT / 128, BKSEL / 128, Ecnt), 256>>>(x, we, be);
    k_combine<<<Bsz, 256>>>(out);
}

// round 7
// speedup vs baseline: 2.9725x; 1.6381x over previous
#include <cuda_runtime.h>
#include <math.h>
#include <stdint.h>

#define Bsz   8192
#define DIN   1024
#define Hdim  128
#define Ecnt  8
#define DOUT  1024
#define BKSEL 2048   // ceil(K*B/E) = ceil(2*8192/8)

// ---------------- scratch (device globals; no runtime allocation) ----------
__device__ float g_h[Bsz * Hdim];            // 4 MB  router hidden
__device__ float g_logits[Bsz * Ecnt];       // 256 KB
__device__ int   g_idx[Ecnt][BKSEL];         // selected token index per (e, slot)
__device__ float g_nws[Ecnt][BKSEL];         // renormalized weights
__device__ int   g_sel_slot[Bsz][Ecnt];      // token,expert -> slot or -1
__device__ float g_eo[(size_t)BKSEL * Ecnt * DOUT]; // 64 MB  [slot][e][d]
__device__ float g_xt[(size_t)Bsz * DIN];            // 32 MB  x pre-rounded to tf32
__device__ float g_wt[(size_t)Ecnt * DIN * DOUT];    // 33.5MB we pre-rounded to tf32

// ---------------------------------------------------------------------------
// helpers
// ---------------------------------------------------------------------------
__device__ __forceinline__ void cp_async16(void* smem, const void* gmem) {
    uint32_t s = (uint32_t)__cvta_generic_to_shared(smem);
    asm volatile("cp.async.cg.shared.global [%0], [%1], 16;\n" :: "r"(s), "l"(gmem));
}
__device__ __forceinline__ uint32_t f2tf32(float v) {
    uint32_t r;
    asm("cvt.rna.tf32.f32 %0, %1;\n" : "=r"(r) : "f"(v));
    return r;
}
__device__ __forceinline__ void mma_tf32(float* cc,
                                         const uint32_t* a, const uint32_t* b) {
    asm volatile(
        "mma.sync.aligned.m16n8k8.row.col.f32.tf32.tf32.f32 "
        "{%0,%1,%2,%3}, {%4,%5,%6,%7}, {%8,%9}, {%0,%1,%2,%3};\n"
        : "+f"(cc[0]), "+f"(cc[1]), "+f"(cc[2]), "+f"(cc[3])
        : "r"(a[0]), "r"(a[1]), "r"(a[2]), "r"(a[3]), "r"(b[0]), "r"(b[1]));
}

// ---------------------------------------------------------------------------
// Kernel 0: pre-round x and we to tf32 bit patterns (hoists all inner-loop cvt)
// ---------------------------------------------------------------------------
__global__ __launch_bounds__(256) void k_cvt(
    const float* __restrict__ x, const float* __restrict__ we)
{
    const int n1 = Bsz * DIN / 4;
    const int n2 = Ecnt * DIN * DOUT / 4;
    for (int i = blockIdx.x * blockDim.x + threadIdx.x; i < n1 + n2;
         i += gridDim.x * blockDim.x) {
        const float4* src;
        float4* dst;
        int j;
        if (i < n1) { src = (const float4*)x;  dst = (float4*)g_xt; j = i; }
        else        { src = (const float4*)we; dst = (float4*)g_wt; j = i - n1; }
        float4 v = src[j];
        v.x = __uint_as_float(f2tf32(v.x));
        v.y = __uint_as_float(f2tf32(v.y));
        v.z = __uint_as_float(f2tf32(v.z));
        v.w = __uint_as_float(f2tf32(v.w));
        dst[j] = v;
    }
}

// ---------------------------------------------------------------------------
// Kernel 1: router hidden h = relu((x@w1+b1) * relu(x@wg+bg)) — full fp32,
// selection-critical. 64 rows x 128 hcols / block; thread tile 8x4 per matrix.
// Warp-uniform X broadcast + stride-1 W loads: 16 LDS per 64 FMA.
// ---------------------------------------------------------------------------
__global__ __launch_bounds__(256) void k_router(
    const float* __restrict__ x,
    const float* __restrict__ w1, const float* __restrict__ b1,
    const float* __restrict__ wg, const float* __restrict__ bg)
{
    __shared__ float Xs[16][64];
    __shared__ float W1s[16][128];
    __shared__ float WGs[16][128];

    const int tid = threadIdx.x;
    const int tx  = tid & 31;     // col lane 0..31
    const int ty  = tid >> 5;     // row lane 0..7 (uniform within a warp)
    const int row0 = blockIdx.x * 64;

    float acc1[8][4];
    float accg[8][4];
#pragma unroll
    for (int i = 0; i < 8; i++)
#pragma unroll
        for (int j = 0; j < 4; j++) { acc1[i][j] = 0.f; accg[i][j] = 0.f; }

    for (int k0 = 0; k0 < DIN; k0 += 16) {
        // X tile: 64 rows x 16 k = 256 float4 -> 1/thread, stored transposed
        {
            int m  = tid >> 2;
            int kq = (tid & 3) << 2;
            float4 v = *(const float4*)(x + (size_t)(row0 + m) * DIN + k0 + kq);
            Xs[kq + 0][m] = v.x; Xs[kq + 1][m] = v.y;
            Xs[kq + 2][m] = v.z; Xs[kq + 3][m] = v.w;
        }
        // W tiles: 16 x 128 each = 512 float4 -> 2/thread each
#pragma unroll
        for (int r = 0; r < 2; r++) {
            int lin = tid + r * 256;
            int kk  = lin >> 5;
            int nq  = (lin & 31) << 2;
            *(float4*)&W1s[kk][nq] = *(const float4*)(w1 + (size_t)(k0 + kk) * Hdim + nq);
            *(float4*)&WGs[kk][nq] = *(const float4*)(wg + (size_t)(k0 + kk) * Hdim + nq);
        }
        __syncthreads();
#pragma unroll
        for (int kk = 0; kk < 16; kk++) {
            float xr[8], w1r[4], wgr[4];
#pragma unroll
            for (int i = 0; i < 8; i++) xr[i] = Xs[kk][i * 8 + ty];   // broadcast
#pragma unroll
            for (int j = 0; j < 4; j++) {
                w1r[j] = W1s[kk][j * 32 + tx];                         // stride-1
                wgr[j] = WGs[kk][j * 32 + tx];
            }
#pragma unroll
            for (int i = 0; i < 8; i++)
#pragma unroll
                for (int j = 0; j < 4; j++) {
                    acc1[i][j] = fmaf(xr[i], w1r[j], acc1[i][j]);
                    accg[i][j] = fmaf(xr[i], wgr[j], accg[i][j]);
                }
        }
        __syncthreads();
    }
#pragma unroll
    for (int i = 0; i < 8; i++) {
        int r = row0 + i * 8 + ty;
#pragma unroll
        for (int j = 0; j < 4; j++) {
            int n = j * 32 + tx;
            float a = acc1[i][j] + b1[n];
            float g = accg[i][j] + bg[n];
            g = fmaxf(g, 0.f);
            float hv = fmaxf(a * g, 0.f);
            g_h[(size_t)r * Hdim + n] = hv;
        }
    }
}

// ---------------------------------------------------------------------------
// Kernel 2: logits = h @ w2 + b2   (one thread per token row)
// ---------------------------------------------------------------------------
__global__ __launch_bounds__(256) void k_logits(
    const float* __restrict__ w2, const float* __restrict__ b2)
{
    __shared__ float W2s[Hdim * Ecnt];
    const int tid = threadIdx.x;
    for (int i = tid; i < Hdim * Ecnt; i += 256) W2s[i] = w2[i];
    __syncthreads();

    const int b = blockIdx.x * 256 + tid;
    float acc[Ecnt];
#pragma unroll
    for (int e = 0; e < Ecnt; e++) acc[e] = b2[e];
    const float* hr = g_h + (size_t)b * Hdim;
#pragma unroll 4
    for (int k = 0; k < Hdim; k++) {
        float hv = hr[k];
#pragma unroll
        for (int e = 0; e < Ecnt; e++) acc[e] = fmaf(hv, W2s[k * Ecnt + e], acc[e]);
    }
#pragma unroll
    for (int e = 0; e < Ecnt; e++) g_logits[(size_t)b * Ecnt + e] = acc[e];
}

// ---------------------------------------------------------------------------
// Kernel 3: per expert — column softmax over batch, exact top-2048 selection.
// Contiguous-index ownership; shuffle reductions; parallel equals collection.
// ---------------------------------------------------------------------------
#define EQ_CAP 1024
__global__ __launch_bounds__(1024) void k_select()
{
    __shared__ float lv[Bsz];        // 32 KB softmax values for this column
    __shared__ float s_warp[32];
    __shared__ int   s_bits[32];     // per-bit bisection counters
    __shared__ unsigned s_cnt;       // count of strictly-greater
    __shared__ int   s_eq[EQ_CAP];   // indices equal to threshold
    __shared__ unsigned s_eqn;
    __shared__ float s_bf;

    const int e    = blockIdx.x;
    const int tid  = threadIdx.x;
    const int lane = tid & 31;
    const int wid  = tid >> 5;

    float loc[8];
#pragma unroll
    for (int r = 0; r < 8; r++) {
        int i = tid * 8 + r;                       // contiguous ownership
        loc[r] = g_logits[(size_t)i * Ecnt + e];
        g_sel_slot[i][e] = -1;
    }
    if (tid < 32) s_bits[tid] = 0;
    if (tid == 0) { s_cnt = 0u; s_eqn = 0u; }

    // --- column max (shuffle + 32 partials) ---
    float m = loc[0];
#pragma unroll
    for (int r = 1; r < 8; r++) m = fmaxf(m, loc[r]);
#pragma unroll
    for (int o = 16; o > 0; o >>= 1) m = fmaxf(m, __shfl_xor_sync(0xffffffffu, m, o));
    if (lane == 0) s_warp[wid] = m;
    __syncthreads();
    if (tid < 32) {
        float v = s_warp[tid];
#pragma unroll
        for (int o = 16; o > 0; o >>= 1) v = fmaxf(v, __shfl_xor_sync(0xffffffffu, v, o));
        if (tid == 0) s_bf = v;
    }
    __syncthreads();
    m = s_bf;
    __syncthreads();

    // --- column sum of exp ---
    float s = 0.f;
#pragma unroll
    for (int r = 0; r < 8; r++) s += expf(loc[r] - m);
#pragma unroll
    for (int o = 16; o > 0; o >>= 1) s += __shfl_xor_sync(0xffffffffu, s, o);
    if (lane == 0) s_warp[wid] = s;
    __syncthreads();
    if (tid < 32) {
        float v = s_warp[tid];
#pragma unroll
        for (int o = 16; o > 0; o >>= 1) v += __shfl_xor_sync(0xffffffffu, v, o);
        if (tid == 0) s_bf = v;
    }
    __syncthreads();
    s = s_bf;
    __syncthreads();

    const float inv_s = 1.0f / s;
    unsigned ub[8];
#pragma unroll
    for (int r = 0; r < 8; r++) {
        float v = expf(loc[r] - m) * inv_s;
        lv[tid * 8 + r] = v;
        ub[r] = __float_as_uint(v);
    }
    __syncthreads();

    // --- radix bisection for V = 2048th largest (values in (0,1): bits 31,30=0)
    unsigned cur = 0u;
    for (int bit = 29; bit >= 0; bit--) {
        unsigned cand = cur | (1u << bit);
        int c = 0;
#pragma unroll
        for (int r = 0; r < 8; r++) c += (ub[r] >= cand) ? 1 : 0;
#pragma unroll
        for (int o = 16; o > 0; o >>= 1) c += __shfl_xor_sync(0xffffffffu, c, o);
        if (lane == 0) atomicAdd(&s_bits[bit], c);
        __syncthreads();
        if (s_bits[bit] >= BKSEL) cur = cand;
    }
    const unsigned V = cur;

    // --- strictly-greater: parallel, unordered (slot order is irrelevant:
    //     output depends only on the selected SET + per-set softmax) ---
#pragma unroll
    for (int r = 0; r < 8; r++) {
        int i = tid * 8 + r;
        if (ub[r] > V) {
            unsigned p = atomicAdd(&s_cnt, 1u);
            g_idx[e][p] = i;
            g_sel_slot[i][e] = (int)p;
        } else if (ub[r] == V) {
            unsigned q = atomicAdd(&s_eqn, 1u);
            if (q < EQ_CAP) s_eq[q] = i;
        }
    }
    __syncthreads();

    const unsigned n_greater = s_cnt;
    const unsigned needed    = BKSEL - n_greater;
    const unsigned eqn       = s_eqn;

    if (eqn == needed && eqn <= EQ_CAP) {
        // common case: all equals are included -> order irrelevant, parallel
        for (unsigned q = tid; q < eqn; q += 1024) {
            int i = s_eq[q];
            unsigned p = n_greater + q;
            g_idx[e][p] = i;
            g_sel_slot[i][e] = (int)p;
        }
    } else if (tid == 0) {
        // rare tie-overflow: take lowest-index equals (matches top_k tie-break)
        unsigned p = n_greater;
        for (int i = 0; i < Bsz && p < BKSEL; i++) {
            if (__float_as_uint(lv[i]) == V) {
                g_idx[e][p] = i;
                g_sel_slot[i][e] = (int)p;
                p++;
            }
        }
    }
    __syncthreads();

    // --- nws = softmax over the 2048 selected weights ---
    float wsv[2];
    float m2 = -1e30f;
#pragma unroll
    for (int r = 0; r < 2; r++) {
        int slot = tid + r * 1024;
        wsv[r] = lv[g_idx[e][slot]];
        m2 = fmaxf(m2, wsv[r]);
    }
#pragma unroll
    for (int o = 16; o > 0; o >>= 1) m2 = fmaxf(m2, __shfl_xor_sync(0xffffffffu, m2, o));
    if (lane == 0) s_warp[wid] = m2;
    __syncthreads();
    if (tid < 32) {
        float v = s_warp[tid];
#pragma unroll
        for (int o = 16; o > 0; o >>= 1) v = fmaxf(v, __shfl_xor_sync(0xffffffffu, v, o));
        if (tid == 0) s_bf = v;
    }
    __syncthreads();
    m2 = s_bf;
    __syncthreads();

    float s2 = expf(wsv[0] - m2) + expf(wsv[1] - m2);
#pragma unroll
    for (int o = 16; o > 0; o >>= 1) s2 += __shfl_xor_sync(0xffffffffu, s2, o);
    if (lane == 0) s_warp[wid] = s2;
    __syncthreads();
    if (tid < 32) {
        float v = s_warp[tid];
#pragma unroll
        for (int o = 16; o > 0; o >>= 1) v += __shfl_xor_sync(0xffffffffu, v, o);
        if (tid == 0) s_bf = v;
    }
    __syncthreads();
    s2 = s_bf;

    const float inv_s2 = 1.0f / s2;
#pragma unroll
    for (int r = 0; r < 2; r++)
        g_nws[e][tid + r * 1024] = expf(wsv[r] - m2) * inv_s2;
}

// ---------------------------------------------------------------------------
// Kernel 4: expert GEMM on tensor cores (tf32 mma.sync m16n8k8):
//   eo[slot, e, :] = (x[idx[e][slot]] @ we[e] + be[e]) * nws[e][slot]
// Operands pre-rounded to tf32 in g_xt/g_wt: inner loop is pure LDS + MMA.
// 128x128 block tile, kb=16, 2-stage cp.async, 8 warps (2m x 4n), 64x32/warp.
// ---------------------------------------------------------------------------
__global__ __launch_bounds__(256, 2) void k_expert(
    const float* __restrict__ be)
{
    __shared__ float As[2][128][20];   // A: [m][k], stride 20 -> conflict-free
    __shared__ float Bs[2][16][136];   // B: [k][n], stride 136 -> conflict-free
    __shared__ int   ridx[128];

    const int e  = blockIdx.z;
    const int m0 = blockIdx.y * 128;
    const int n0 = blockIdx.x * 128;
    const int tid  = threadIdx.x;
    const int lane = tid & 31;
    const int w    = tid >> 5;
    const int wm   = w & 1;        // warp row (0..1) -> 64 rows
    const int wn   = w >> 1;       // warp col (0..3) -> 32 cols
    const int g    = lane >> 2;    // group id 0..7
    const int c    = lane & 3;     // thread-in-group 0..3

    if (tid < 128) ridx[tid] = g_idx[e][m0 + tid];
    __syncthreads();

    const float* weE = g_wt + (size_t)e * DIN * DOUT + n0;

    float acc[4][4][4];
#pragma unroll
    for (int mi = 0; mi < 4; mi++)
#pragma unroll
        for (int nj = 0; nj < 4; nj++)
#pragma unroll
            for (int q = 0; q < 4; q++) acc[mi][nj][q] = 0.f;

#define LOAD_STAGE(buf, k0)                                                    \
    do {                                                                       \
        _Pragma("unroll")                                                      \
        for (int s_ = 0; s_ < 2; s_++) {                                       \
            int lin = tid + s_ * 256;                                          \
            int row = lin >> 2, col = (lin & 3) << 2;                          \
            cp_async16(&As[buf][row][col],                                     \
                       g_xt + (size_t)ridx[row] * DIN + (k0) + col);           \
        }                                                                      \
        _Pragma("unroll")                                                      \
        for (int s_ = 0; s_ < 2; s_++) {                                       \
            int lin = tid + s_ * 256;                                          \
            int kk_ = lin >> 5, col = (lin & 31) << 2;                         \
            cp_async16(&Bs[buf][kk_][col],                                     \
                       weE + (size_t)((k0) + kk_) * DOUT + col);               \
        }                                                                      \
        asm volatile("cp.async.commit_group;\n");                              \
    } while (0)

    LOAD_STAGE(0, 0);

    const int NT = DIN / 16;   // 64 iterations
    for (int t = 0; t < NT; t++) {
        int buf = t & 1;
        if (t + 1 < NT) {
            LOAD_STAGE(buf ^ 1, (t + 1) * 16);
            asm volatile("cp.async.wait_group 1;\n");
        } else {
            asm volatile("cp.async.wait_group 0;\n");
        }
        __syncthreads();

#pragma unroll
        for (int kk = 0; kk < 2; kk++) {        // two k8 steps per kb=16
            uint32_t aF[4][4];
            uint32_t bF[4][2];
            const int kb8 = kk * 8;
#pragma unroll
            for (int mi = 0; mi < 4; mi++) {
                int row = wm * 64 + mi * 16 + g;
                aF[mi][0] = __float_as_uint(As[buf][row    ][kb8 + c    ]);
                aF[mi][1] = __float_as_uint(As[buf][row + 8][kb8 + c    ]);
                aF[mi][2] = __float_as_uint(As[buf][row    ][kb8 + c + 4]);
                aF[mi][3] = __float_as_uint(As[buf][row + 8][kb8 + c + 4]);
            }
#pragma unroll
            for (int nj = 0; nj < 4; nj++) {
                int nn = wn * 32 + nj * 8 + g;
                bF[nj][0] = __float_as_uint(Bs[buf][kb8 + c    ][nn]);
                bF[nj][1] = __float_as_uint(Bs[buf][kb8 + c + 4][nn]);
            }
#pragma unroll
            for (int mi = 0; mi < 4; mi++)
#pragma unroll
                for (int nj = 0; nj < 4; nj++)
                    mma_tf32(acc[mi][nj], aF[mi], bF[nj]);
        }
        __syncthreads();
    }
#undef LOAD_STAGE

    const float* beE = be + (size_t)e * DOUT + n0;
#pragma unroll
    for (int mi = 0; mi < 4; mi++) {
        int slot0 = m0 + wm * 64 + mi * 16 + g;
        int slot1 = slot0 + 8;
        float nw0 = g_nws[e][slot0];
        float nw1 = g_nws[e][slot1];
        float* o0 = g_eo + ((size_t)slot0 * Ecnt + e) * DOUT + n0;
        float* o1 = g_eo + ((size_t)slot1 * Ecnt + e) * DOUT + n0;
#pragma unroll
        for (int nj = 0; nj < 4; nj++) {
            int n = wn * 32 + nj * 8 + c * 2;
            float bb0 = beE[n], bb1 = beE[n + 1];
            float2 v0, v1;
            v0.x = (acc[mi][nj][0] + bb0) * nw0;
            v0.y = (acc[mi][nj][1] + bb1) * nw0;
            v1.x = (acc[mi][nj][2] + bb0) * nw1;
            v1.y = (acc[mi][nj][3] + bb1) * nw1;
            *(float2*)(o0 + n) = v0;
            *(float2*)(o1 + n) = v1;
        }
    }
}

// ---------------------------------------------------------------------------
// Kernel 5: combine. For token row b:
//   out[b, e*DOUT + d] = c_e[d] + sum_e' c_e'[d]   (no atomics needed)
// ---------------------------------------------------------------------------
__global__ __launch_bounds__(256) void k_combine(float* __restrict__ out)
{
    __shared__ int slots[Ecnt];
    const int b   = blockIdx.x;
    const int tid = threadIdx.x;
    if (tid < Ecnt) slots[tid] = g_sel_slot[b][tid];
    __syncthreads();

#pragma unroll
    for (int r = 0; r < 4; r++) {
        int d = tid + r * 256;
        float cv[Ecnt];
        float ssum = 0.f;
#pragma unroll
        for (int e = 0; e < Ecnt; e++) {
            int slot = slots[e];
            float v = 0.f;
            if (slot >= 0) v = g_eo[((size_t)slot * Ecnt + e) * DOUT + d];
            cv[e] = v;
            ssum += v;
        }
        float* orow = out + (size_t)b * (Ecnt * DOUT) + d;
#pragma unroll
        for (int e = 0; e < Ecnt; e++)
            orow[(size_t)e * DOUT] = cv[e] + ssum;
    }
}

// ---------------------------------------------------------------------------
extern "C" void kernel_launch(void* const* d_in, const int* in_sizes, int n_in,
                              void* d_out, int out_size)
{
    const float* x  = (const float*)d_in[0];
    const float* w1 = (const float*)d_in[1];
    const float* b1 = (const float*)d_in[2];
    const float* wg = (const float*)d_in[3];
    const float* bg = (const float*)d_in[4];
    const float* w2 = (const float*)d_in[5];
    const float* b2 = (const float*)d_in[6];
    const float* we = (const float*)d_in[7];
    const float* be = (const float*)d_in[8];
    float* out = (float*)d_out;

    k_cvt<<<1184, 256>>>(x, we);
    k_router<<<Bsz / 64, 256>>>(x, w1, b1, wg, bg);
    k_logits<<<Bsz / 256, 256>>>(w2, b2);
    k_select<<<Ecnt, 1024>>>();
    k_expert<<<dim3(DOUT / 128, BKSEL / 128, Ecnt), 256>>>(be);
    k_combine<<<Bsz, 256>>>(out);
}

// round 8
// speedup vs baseline: 2.9884x; 1.0054x over previous
#include <cuda_runtime.h>
#include <math.h>
#include <stdint.h>

#define Bsz   8192
#define DIN   1024
#define Hdim  128
#define Ecnt  8
#define DOUT  1024
#define BKSEL 2048   // ceil(K*B/E) = ceil(2*8192/8)

// ---------------- scratch (device globals; no runtime allocation) ----------
__device__ float g_logits[Bsz * Ecnt];       // 256 KB
__device__ int   g_idx[Ecnt][BKSEL];         // selected token index per (e, slot)
__device__ float g_nws[Ecnt][BKSEL];         // renormalized weights
__device__ int   g_sel_slot[Bsz][Ecnt];      // token,expert -> slot or -1
__device__ float g_eo[(size_t)BKSEL * Ecnt * DOUT]; // 64 MB  [slot][e][d]
__device__ float g_xt[(size_t)Bsz * DIN];            // 32 MB  x pre-rounded to tf32
__device__ float g_wt[(size_t)Ecnt * DIN * DOUT];    // 33.5MB we pre-rounded to tf32

// ---------------------------------------------------------------------------
// helpers
// ---------------------------------------------------------------------------
__device__ __forceinline__ void cp_async16(void* smem, const void* gmem) {
    uint32_t s = (uint32_t)__cvta_generic_to_shared(smem);
    asm volatile("cp.async.cg.shared.global [%0], [%1], 16;\n" :: "r"(s), "l"(gmem));
}
__device__ __forceinline__ uint32_t f2tf32(float v) {
    uint32_t r;
    asm("cvt.rna.tf32.f32 %0, %1;\n" : "=r"(r) : "f"(v));
    return r;
}
__device__ __forceinline__ void mma_tf32(float* cc,
                                         const uint32_t* a, const uint32_t* b) {
    asm volatile(
        "mma.sync.aligned.m16n8k8.row.col.f32.tf32.tf32.f32 "
        "{%0,%1,%2,%3}, {%4,%5,%6,%7}, {%8,%9}, {%0,%1,%2,%3};\n"
        : "+f"(cc[0]), "+f"(cc[1]), "+f"(cc[2]), "+f"(cc[3])
        : "r"(a[0]), "r"(a[1]), "r"(a[2]), "r"(a[3]), "r"(b[0]), "r"(b[1]));
}

// ---------------------------------------------------------------------------
// Kernel 0: pre-round x and we to tf32 bit patterns (hoists all inner-loop cvt)
// ---------------------------------------------------------------------------
__global__ __launch_bounds__(256) void k_cvt(
    const float* __restrict__ x, const float* __restrict__ we)
{
    const int n1 = Bsz * DIN / 4;
    const int n2 = Ecnt * DIN * DOUT / 4;
    for (int i = blockIdx.x * blockDim.x + threadIdx.x; i < n1 + n2;
         i += gridDim.x * blockDim.x) {
        const float4* src;
        float4* dst;
        int j;
        if (i < n1) { src = (const float4*)x;  dst = (float4*)g_xt; j = i; }
        else        { src = (const float4*)we; dst = (float4*)g_wt; j = i - n1; }
        float4 v = src[j];
        v.x = __uint_as_float(f2tf32(v.x));
        v.y = __uint_as_float(f2tf32(v.y));
        v.z = __uint_as_float(f2tf32(v.z));
        v.w = __uint_as_float(f2tf32(v.w));
        dst[j] = v;
    }
}

// ---------------------------------------------------------------------------
// Kernel 1: router fused — h = relu((x@w1+b1) * relu(x@wg+bg)) staged in smem,
// then logits = h @ w2 + b2 computed in the epilogue (4-lane shfl reduce).
// Full fp32 throughout (selection-critical).
// ---------------------------------------------------------------------------
__global__ __launch_bounds__(256) void k_router(
    const float* __restrict__ x,
    const float* __restrict__ w1, const float* __restrict__ b1,
    const float* __restrict__ wg, const float* __restrict__ bg,
    const float* __restrict__ w2, const float* __restrict__ b2)
{
    __shared__ float Xs[16][64];
    __shared__ float W1s[16][128];
    __shared__ float WGs[16][128];
    __shared__ float Hs[64][132];         // padded: epilogue reads conflict-lite
    __shared__ float W2s[Hdim * Ecnt];    // 4 KB

    const int tid = threadIdx.x;
    const int tx  = tid & 31;     // col lane 0..31
    const int ty  = tid >> 5;     // row lane 0..7 (uniform within a warp)
    const int row0 = blockIdx.x * 64;

    float acc1[8][4];
    float accg[8][4];
#pragma unroll
    for (int i = 0; i < 8; i++)
#pragma unroll
        for (int j = 0; j < 4; j++) { acc1[i][j] = 0.f; accg[i][j] = 0.f; }

    for (int k0 = 0; k0 < DIN; k0 += 16) {
        {
            int m  = tid >> 2;
            int kq = (tid & 3) << 2;
            float4 v = *(const float4*)(x + (size_t)(row0 + m) * DIN + k0 + kq);
            Xs[kq + 0][m] = v.x; Xs[kq + 1][m] = v.y;
            Xs[kq + 2][m] = v.z; Xs[kq + 3][m] = v.w;
        }
#pragma unroll
        for (int r = 0; r < 2; r++) {
            int lin = tid + r * 256;
            int kk  = lin >> 5;
            int nq  = (lin & 31) << 2;
            *(float4*)&W1s[kk][nq] = *(const float4*)(w1 + (size_t)(k0 + kk) * Hdim + nq);
            *(float4*)&WGs[kk][nq] = *(const float4*)(wg + (size_t)(k0 + kk) * Hdim + nq);
        }
        __syncthreads();
#pragma unroll
        for (int kk = 0; kk < 16; kk++) {
            float xr[8], w1r[4], wgr[4];
#pragma unroll
            for (int i = 0; i < 8; i++) xr[i] = Xs[kk][i * 8 + ty];   // broadcast
#pragma unroll
            for (int j = 0; j < 4; j++) {
                w1r[j] = W1s[kk][j * 32 + tx];                         // stride-1
                wgr[j] = WGs[kk][j * 32 + tx];
            }
#pragma unroll
            for (int i = 0; i < 8; i++)
#pragma unroll
                for (int j = 0; j < 4; j++) {
                    acc1[i][j] = fmaf(xr[i], w1r[j], acc1[i][j]);
                    accg[i][j] = fmaf(xr[i], wgr[j], accg[i][j]);
                }
        }
        __syncthreads();
    }

    // GLU epilogue -> h tile into smem
#pragma unroll
    for (int i = 0; i < 8; i++) {
#pragma unroll
        for (int j = 0; j < 4; j++) {
            int n = j * 32 + tx;
            float a = acc1[i][j] + b1[n];
            float g = accg[i][j] + bg[n];
            g = fmaxf(g, 0.f);
            Hs[i * 8 + ty][n] = fmaxf(a * g, 0.f);
        }
    }
    // stage w2
    for (int i = tid; i < Hdim * Ecnt; i += 256) W2s[i] = w2[i];
    __syncthreads();

    // logits for 64 rows: thread (r = tid>>2, q = tid&3) sums 32 n's, then
    // 4-lane shuffle reduce (lanes 4r'..4r'+3 are consecutive in the warp).
    {
        const int r = tid >> 2;
        const int q = tid & 3;
        float acc[Ecnt];
#pragma unroll
        for (int e = 0; e < Ecnt; e++) acc[e] = 0.f;
#pragma unroll 4
        for (int k = 0; k < 32; k++) {
            int n = q * 32 + k;
            float hv = Hs[r][n];
#pragma unroll
            for (int e = 0; e < Ecnt; e++)
                acc[e] = fmaf(hv, W2s[n * Ecnt + e], acc[e]);
        }
#pragma unroll
        for (int e = 0; e < Ecnt; e++) {
            acc[e] += __shfl_xor_sync(0xffffffffu, acc[e], 1);
            acc[e] += __shfl_xor_sync(0xffffffffu, acc[e], 2);
        }
        if (q == 0) {
#pragma unroll
            for (int e = 0; e < Ecnt; e++)
                g_logits[(size_t)(row0 + r) * Ecnt + e] = acc[e] + b2[e];
        }
    }
}

// ---------------------------------------------------------------------------
// Kernel 3: per expert — column softmax over batch, exact top-2048 selection.
// Contiguous-index ownership; shuffle reductions; parallel equals collection.
// ---------------------------------------------------------------------------
#define EQ_CAP 1024
__global__ __launch_bounds__(1024) void k_select()
{
    __shared__ float lv[Bsz];        // 32 KB softmax values for this column
    __shared__ float s_warp[32];
    __shared__ int   s_bits[32];     // per-bit bisection counters
    __shared__ unsigned s_cnt;       // count of strictly-greater
    __shared__ int   s_eq[EQ_CAP];   // indices equal to threshold
    __shared__ unsigned s_eqn;
    __shared__ float s_bf;

    const int e    = blockIdx.x;
    const int tid  = threadIdx.x;
    const int lane = tid & 31;
    const int wid  = tid >> 5;

    float loc[8];
#pragma unroll
    for (int r = 0; r < 8; r++) {
        int i = tid * 8 + r;                       // contiguous ownership
        loc[r] = g_logits[(size_t)i * Ecnt + e];
        g_sel_slot[i][e] = -1;
    }
    if (tid < 32) s_bits[tid] = 0;
    if (tid == 0) { s_cnt = 0u; s_eqn = 0u; }

    // --- column max (shuffle + 32 partials) ---
    float m = loc[0];
#pragma unroll
    for (int r = 1; r < 8; r++) m = fmaxf(m, loc[r]);
#pragma unroll
    for (int o = 16; o > 0; o >>= 1) m = fmaxf(m, __shfl_xor_sync(0xffffffffu, m, o));
    if (lane == 0) s_warp[wid] = m;
    __syncthreads();
    if (tid < 32) {
        float v = s_warp[tid];
#pragma unroll
        for (int o = 16; o > 0; o >>= 1) v = fmaxf(v, __shfl_xor_sync(0xffffffffu, v, o));
        if (tid == 0) s_bf = v;
    }
    __syncthreads();
    m = s_bf;
    __syncthreads();

    // --- column sum of exp ---
    float s = 0.f;
#pragma unroll
    for (int r = 0; r < 8; r++) s += expf(loc[r] - m);
#pragma unroll
    for (int o = 16; o > 0; o >>= 1) s += __shfl_xor_sync(0xffffffffu, s, o);
    if (lane == 0) s_warp[wid] = s;
    __syncthreads();
    if (tid < 32) {
        float v = s_warp[tid];
#pragma unroll
        for (int o = 16; o > 0; o >>= 1) v += __shfl_xor_sync(0xffffffffu, v, o);
        if (tid == 0) s_bf = v;
    }
    __syncthreads();
    s = s_bf;
    __syncthreads();

    const float inv_s = 1.0f / s;
    unsigned ub[8];
#pragma unroll
    for (int r = 0; r < 8; r++) {
        float v = expf(loc[r] - m) * inv_s;
        lv[tid * 8 + r] = v;
        ub[r] = __float_as_uint(v);
    }
    __syncthreads();

    // --- radix bisection for V = 2048th largest (values in (0,1): bits 31,30=0)
    unsigned cur = 0u;
    for (int bit = 29; bit >= 0; bit--) {
        unsigned cand = cur | (1u << bit);
        int c = 0;
#pragma unroll
        for (int r = 0; r < 8; r++) c += (ub[r] >= cand) ? 1 : 0;
#pragma unroll
        for (int o = 16; o > 0; o >>= 1) c += __shfl_xor_sync(0xffffffffu, c, o);
        if (lane == 0) atomicAdd(&s_bits[bit], c);
        __syncthreads();
        if (s_bits[bit] >= BKSEL) cur = cand;
    }
    const unsigned V = cur;

    // --- strictly-greater: parallel, unordered (slot order is irrelevant:
    //     output depends only on the selected SET + per-set softmax) ---
#pragma unroll
    for (int r = 0; r < 8; r++) {
        int i = tid * 8 + r;
        if (ub[r] > V) {
            unsigned p = atomicAdd(&s_cnt, 1u);
            g_idx[e][p] = i;
            g_sel_slot[i][e] = (int)p;
        } else if (ub[r] == V) {
            unsigned q = atomicAdd(&s_eqn, 1u);
            if (q < EQ_CAP) s_eq[q] = i;
        }
    }
    __syncthreads();

    const unsigned n_greater = s_cnt;
    const unsigned needed    = BKSEL - n_greater;
    const unsigned eqn       = s_eqn;

    if (eqn == needed && eqn <= EQ_CAP) {
        // common case: all equals are included -> order irrelevant, parallel
        for (unsigned q = tid; q < eqn; q += 1024) {
            int i = s_eq[q];
            unsigned p = n_greater + q;
            g_idx[e][p] = i;
            g_sel_slot[i][e] = (int)p;
        }
    } else if (tid == 0) {
        // rare tie-overflow: take lowest-index equals (matches top_k tie-break)
        unsigned p = n_greater;
        for (int i = 0; i < Bsz && p < BKSEL; i++) {
            if (__float_as_uint(lv[i]) == V) {
                g_idx[e][p] = i;
                g_sel_slot[i][e] = (int)p;
                p++;
            }
        }
    }
    __syncthreads();

    // --- nws = softmax over the 2048 selected weights ---
    float wsv[2];
    float m2 = -1e30f;
#pragma unroll
    for (int r = 0; r < 2; r++) {
        int slot = tid + r * 1024;
        wsv[r] = lv[g_idx[e][slot]];
        m2 = fmaxf(m2, wsv[r]);
    }
#pragma unroll
    for (int o = 16; o > 0; o >>= 1) m2 = fmaxf(m2, __shfl_xor_sync(0xffffffffu, m2, o));
    if (lane == 0) s_warp[wid] = m2;
    __syncthreads();
    if (tid < 32) {
        float v = s_warp[tid];
#pragma unroll
        for (int o = 16; o > 0; o >>= 1) v = fmaxf(v, __shfl_xor_sync(0xffffffffu, v, o));
        if (tid == 0) s_bf = v;
    }
    __syncthreads();
    m2 = s_bf;
    __syncthreads();

    float s2 = expf(wsv[0] - m2) + expf(wsv[1] - m2);
#pragma unroll
    for (int o = 16; o > 0; o >>= 1) s2 += __shfl_xor_sync(0xffffffffu, s2, o);
    if (lane == 0) s_warp[wid] = s2;
    __syncthreads();
    if (tid < 32) {
        float v = s_warp[tid];
#pragma unroll
        for (int o = 16; o > 0; o >>= 1) v += __shfl_xor_sync(0xffffffffu, v, o);
        if (tid == 0) s_bf = v;
    }
    __syncthreads();
    s2 = s_bf;

    const float inv_s2 = 1.0f / s2;
#pragma unroll
    for (int r = 0; r < 2; r++)
        g_nws[e][tid + r * 1024] = expf(wsv[r] - m2) * inv_s2;
}

// ---------------------------------------------------------------------------
// Kernel 4: expert GEMM on tensor cores (tf32 mma.sync m16n8k8):
//   eo[slot, e, :] = (x[idx[e][slot]] @ we[e] + be[e]) * nws[e][slot]
// Pre-rounded operands; 128x128 tile, kb=16, 3-stage cp.async ring with ONE
// __syncthreads per iteration; 8 warps (2m x 4n), 64x32/warp.
// ---------------------------------------------------------------------------
__global__ __launch_bounds__(256, 2) void k_expert(
    const float* __restrict__ be)
{
    __shared__ float As[3][128][20];   // A: [m][k], stride 20 -> conflict-free
    __shared__ float Bs[3][16][136];   // B: [k][n], stride 136 -> conflict-free
    __shared__ int   ridx[128];

    const int e  = blockIdx.z;
    const int m0 = blockIdx.y * 128;
    const int n0 = blockIdx.x * 128;
    const int tid  = threadIdx.x;
    const int lane = tid & 31;
    const int w    = tid >> 5;
    const int wm   = w & 1;        // warp row (0..1) -> 64 rows
    const int wn   = w >> 1;       // warp col (0..3) -> 32 cols
    const int g    = lane >> 2;    // group id 0..7
    const int c    = lane & 3;     // thread-in-group 0..3

    if (tid < 128) ridx[tid] = g_idx[e][m0 + tid];
    __syncthreads();

    const float* weE = g_wt + (size_t)e * DIN * DOUT + n0;

    float acc[4][4][4];
#pragma unroll
    for (int mi = 0; mi < 4; mi++)
#pragma unroll
        for (int nj = 0; nj < 4; nj++)
#pragma unroll
            for (int q = 0; q < 4; q++) acc[mi][nj][q] = 0.f;

#define LOAD_STAGE(buf, k0)                                                    \
    do {                                                                       \
        _Pragma("unroll")                                                      \
        for (int s_ = 0; s_ < 2; s_++) {                                       \
            int lin = tid + s_ * 256;                                          \
            int row = lin >> 2, col = (lin & 3) << 2;                          \
            cp_async16(&As[buf][row][col],                                     \
                       g_xt + (size_t)ridx[row] * DIN + (k0) + col);           \
        }                                                                      \
        _Pragma("unroll")                                                      \
        for (int s_ = 0; s_ < 2; s_++) {                                       \
            int lin = tid + s_ * 256;                                          \
            int kk_ = lin >> 5, col = (lin & 31) << 2;                         \
            cp_async16(&Bs[buf][kk_][col],                                     \
                       weE + (size_t)((k0) + kk_) * DOUT + col);               \
        }                                                                      \
        asm volatile("cp.async.commit_group;\n");                              \
    } while (0)

    LOAD_STAGE(0, 0);
    LOAD_STAGE(1, 16);

    const int NT = DIN / 16;   // 64 iterations
    int buf = 0, nbuf = 2;     // buf: compute stage; nbuf: stage to fill
    for (int t = 0; t < NT; t++) {
        if (t + 2 < NT) {
            asm volatile("cp.async.wait_group 1;\n");
            __syncthreads();                  // all warps done with nbuf's prior use
            LOAD_STAGE(nbuf, (t + 2) * 16);
        } else {
            asm volatile("cp.async.wait_group 0;\n");
            __syncthreads();
        }

#pragma unroll
        for (int kk = 0; kk < 2; kk++) {        // two k8 steps per kb=16
            uint32_t aF[4][4];
            uint32_t bF[4][2];
            const int kb8 = kk * 8;
#pragma unroll
            for (int mi = 0; mi < 4; mi++) {
                int row = wm * 64 + mi * 16 + g;
                aF[mi][0] = __float_as_uint(As[buf][row    ][kb8 + c    ]);
                aF[mi][1] = __float_as_uint(As[buf][row + 8][kb8 + c    ]);
                aF[mi][2] = __float_as_uint(As[buf][row    ][kb8 + c + 4]);
                aF[mi][3] = __float_as_uint(As[buf][row + 8][kb8 + c + 4]);
            }
#pragma unroll
            for (int nj = 0; nj < 4; nj++) {
                int nn = wn * 32 + nj * 8 + g;
                bF[nj][0] = __float_as_uint(Bs[buf][kb8 + c    ][nn]);
                bF[nj][1] = __float_as_uint(Bs[buf][kb8 + c + 4][nn]);
            }
#pragma unroll
            for (int mi = 0; mi < 4; mi++)
#pragma unroll
                for (int nj = 0; nj < 4; nj++)
                    mma_tf32(acc[mi][nj], aF[mi], bF[nj]);
        }
        buf++;  if (buf == 3)  buf = 0;
        nbuf++; if (nbuf == 3) nbuf = 0;
    }
#undef LOAD_STAGE

    const float* beE = be + (size_t)e * DOUT + n0;
#pragma unroll
    for (int mi = 0; mi < 4; mi++) {
        int slot0 = m0 + wm * 64 + mi * 16 + g;
        int slot1 = slot0 + 8;
        float nw0 = g_nws[e][slot0];
        float nw1 = g_nws[e][slot1];
        float* o0 = g_eo + ((size_t)slot0 * Ecnt + e) * DOUT + n0;
        float* o1 = g_eo + ((size_t)slot1 * Ecnt + e) * DOUT + n0;
#pragma unroll
        for (int nj = 0; nj < 4; nj++) {
            int n = wn * 32 + nj * 8 + c * 2;
            float bb0 = beE[n], bb1 = beE[n + 1];
            float2 v0, v1;
            v0.x = (acc[mi][nj][0] + bb0) * nw0;
            v0.y = (acc[mi][nj][1] + bb1) * nw0;
            v1.x = (acc[mi][nj][2] + bb0) * nw1;
            v1.y = (acc[mi][nj][3] + bb1) * nw1;
            *(float2*)(o0 + n) = v0;
            *(float2*)(o1 + n) = v1;
        }
    }
}

// ---------------------------------------------------------------------------
// Kernel 5: combine (float4 vectorized). For token row b:
//   out[b, e*DOUT + d] = c_e[d] + sum_e' c_e'[d]   (no atomics needed)
// ---------------------------------------------------------------------------
__global__ __launch_bounds__(256) void k_combine(float* __restrict__ out)
{
    __shared__ int slots[Ecnt];
    const int b   = blockIdx.x;
    const int tid = threadIdx.x;
    if (tid < Ecnt) slots[tid] = g_sel_slot[b][tid];
    __syncthreads();

    const int d = tid * 4;                 // 256 threads x 4 = 1024 = DOUT
    float4 cv[Ecnt];
    float4 ssum = make_float4(0.f, 0.f, 0.f, 0.f);
#pragma unroll
    for (int e = 0; e < Ecnt; e++) {
        int slot = slots[e];
        float4 v = make_float4(0.f, 0.f, 0.f, 0.f);
        if (slot >= 0)
            v = *(const float4*)(g_eo + ((size_t)slot * Ecnt + e) * DOUT + d);
        cv[e] = v;
        ssum.x += v.x; ssum.y += v.y; ssum.z += v.z; ssum.w += v.w;
    }
    float* orow = out + (size_t)b * (Ecnt * DOUT) + d;
#pragma unroll
    for (int e = 0; e < Ecnt; e++) {
        float4 o;
        o.x = cv[e].x + ssum.x;
        o.y = cv[e].y + ssum.y;
        o.z = cv[e].z + ssum.z;
        o.w = cv[e].w + ssum.w;
        *(float4*)(orow + (size_t)e * DOUT) = o;
    }
}

// ---------------------------------------------------------------------------
extern "C" void kernel_launch(void* const* d_in, const int* in_sizes, int n_in,
                              void* d_out, int out_size)
{
    const float* x  = (const float*)d_in[0];
    const float* w1 = (const float*)d_in[1];
    const float* b1 = (const float*)d_in[2];
    const float* wg = (const float*)d_in[3];
    const float* bg = (const float*)d_in[4];
    const float* w2 = (const float*)d_in[5];
    const float* b2 = (const float*)d_in[6];
    const float* we = (const float*)d_in[7];
    const float* be = (const float*)d_in[8];
    float* out = (float*)d_out;

    k_cvt<<<1184, 256>>>(x, we);
    k_router<<<Bsz / 64, 256>>>(x, w1, b1, wg, bg, w2, b2);
    k_select<<<Ecnt, 1024>>>();
    k_expert<<<dim3(DOUT / 128, BKSEL / 128, Ecnt), 256>>>(be);
    k_combine<<<Bsz, 256>>>(out);
}

// round 11
// speedup vs baseline: 3.0737x; 1.0285x over previous
#include <cuda_runtime.h>
#include <math.h>
#include <stdint.h>

#define Bsz   8192
#define DIN   1024
#define Hdim  128
#define Ecnt  8
#define DOUT  1024
#define BKSEL 2048   // ceil(K*B/E) = ceil(2*8192/8)

// ---------------- scratch (device globals; no runtime allocation) ----------
__device__ float g_logits[Bsz * Ecnt];
__device__ int   g_idx[Ecnt][BKSEL];
__device__ float g_nws[Ecnt][BKSEL];
__device__ int   g_sel_slot[Bsz][Ecnt];
__device__ float g_eo[(size_t)BKSEL * Ecnt * DOUT]; // 64 MB [slot][e][d]
__device__ float g_xt[(size_t)Bsz * DIN];           // x, tf32-rounded (by router)
__device__ float g_wt[(size_t)Ecnt * DIN * DOUT];   // we [e][k][n], tf32-rounded

// ---------------------------------------------------------------------------
// helpers
// ---------------------------------------------------------------------------
__device__ __forceinline__ void cp_async16(void* smem, const void* gmem) {
    uint32_t s = (uint32_t)__cvta_generic_to_shared(smem);
    asm volatile("cp.async.cg.shared.global [%0], [%1], 16;\n" :: "r"(s), "l"(gmem));
}
__device__ __forceinline__ uint32_t f2tf32(float v) {
    uint32_t r;
    asm("cvt.rna.tf32.f32 %0, %1;\n" : "=r"(r) : "f"(v));
    return r;
}
__device__ __forceinline__ void mma_tf32(float* cc,
                                         const uint32_t* a, const uint32_t* b) {
    asm volatile(
        "mma.sync.aligned.m16n8k8.row.col.f32.tf32.tf32.f32 "
        "{%0,%1,%2,%3}, {%4,%5,%6,%7}, {%8,%9}, {%0,%1,%2,%3};\n"
        : "+f"(cc[0]), "+f"(cc[1]), "+f"(cc[2]), "+f"(cc[3])
        : "r"(a[0]), "r"(a[1]), "r"(a[2]), "r"(a[3]), "r"(b[0]), "r"(b[1]));
}
// packed dual-fp32 FMA (Blackwell FFMA2). Per-lane IEEE fp32 fma.
__device__ __forceinline__ void fma_x2(uint64_t& acc, uint64_t a, uint64_t b) {
    asm("fma.rn.f32x2 %0, %1, %2, %0;" : "+l"(acc) : "l"(a), "l"(b));
}
__device__ __forceinline__ uint64_t splat_x2(float v) {
    uint64_t r;
    uint32_t u = __float_as_uint(v);
    asm("mov.b64 %0, {%1, %1};" : "=l"(r) : "r"(u));
    return r;
}

// ---------------------------------------------------------------------------
// Kernel 0: we -> g_wt (tf32-rounded, same layout [e][k][n])
// ---------------------------------------------------------------------------
__global__ __launch_bounds__(256) void k_cvtw(const float* __restrict__ we)
{
    const size_t n = (size_t)Ecnt * DIN * DOUT / 4;
    for (size_t i = (size_t)blockIdx.x * blockDim.x + threadIdx.x; i < n;
         i += (size_t)gridDim.x * blockDim.x) {
        float4 v = ((const float4*)we)[i];
        v.x = __uint_as_float(f2tf32(v.x));
        v.y = __uint_as_float(f2tf32(v.y));
        v.z = __uint_as_float(f2tf32(v.z));
        v.w = __uint_as_float(f2tf32(v.w));
        ((float4*)g_wt)[i] = v;
    }
}

// ---------------------------------------------------------------------------
// Kernel 1: router fused — h = relu((x@w1+b1) * relu(x@wg+bg)) staged in smem,
// then logits = h @ w2 + b2 in the epilogue. Full fp32 via packed FFMA2
// (fma.rn.f32x2): per-lane math bit-identical to scalar fp32 FMA, 2x issue.
// Also emits g_xt = tf32-rounded x.
// ---------------------------------------------------------------------------
__global__ __launch_bounds__(256) void k_router(
    const float* __restrict__ x,
    const float* __restrict__ w1, const float* __restrict__ b1,
    const float* __restrict__ wg, const float* __restrict__ bg,
    const float* __restrict__ w2, const float* __restrict__ b2)
{
    __shared__ float Xs[16][64];
    __shared__ float W1s[16][128];
    __shared__ float WGs[16][128];
    __shared__ float Hs[64][132];
    __shared__ float W2s[Hdim * Ecnt];

    const int tid = threadIdx.x;
    const int tx  = tid & 31;     // col lane 0..31
    const int ty  = tid >> 5;     // warp id 0..7 (row group)
    const int row0 = blockIdx.x * 64;

    // acc pairs: rows i=0..7 (m = i*8+ty), col pairs j2=0..1 (n = j2*64 + 2*tx +{0,1})
    uint64_t acc1p[8][2];
    uint64_t accgp[8][2];
#pragma unroll
    for (int i = 0; i < 8; i++)
#pragma unroll
        for (int j2 = 0; j2 < 2; j2++) { acc1p[i][j2] = 0ull; accgp[i][j2] = 0ull; }

    for (int k0 = 0; k0 < DIN; k0 += 16) {
        {
            int m  = tid >> 2;
            int kq = (tid & 3) << 2;
            float4 v = *(const float4*)(x + (size_t)(row0 + m) * DIN + k0 + kq);
            Xs[kq + 0][m] = v.x; Xs[kq + 1][m] = v.y;
            Xs[kq + 2][m] = v.z; Xs[kq + 3][m] = v.w;
            float4 vr;
            vr.x = __uint_as_float(f2tf32(v.x));
            vr.y = __uint_as_float(f2tf32(v.y));
            vr.z = __uint_as_float(f2tf32(v.z));
            vr.w = __uint_as_float(f2tf32(v.w));
            *(float4*)(g_xt + (size_t)(row0 + m) * DIN + k0 + kq) = vr;
        }
#pragma unroll
        for (int r = 0; r < 2; r++) {
            int lin = tid + r * 256;
            int kk  = lin >> 5;
            int nq  = (lin & 31) << 2;
            *(float4*)&W1s[kk][nq] = *(const float4*)(w1 + (size_t)(k0 + kk) * Hdim + nq);
            *(float4*)&WGs[kk][nq] = *(const float4*)(wg + (size_t)(k0 + kk) * Hdim + nq);
        }
        __syncthreads();
#pragma unroll
        for (int kk = 0; kk < 16; kk++) {
            uint64_t xp[8];
#pragma unroll
            for (int i = 0; i < 8; i++) xp[i] = splat_x2(Xs[kk][i * 8 + ty]);
            uint64_t w1p[2], wgp[2];
#pragma unroll
            for (int j2 = 0; j2 < 2; j2++) {
                w1p[j2] = *(const uint64_t*)&W1s[kk][j2 * 64 + 2 * tx];  // LDS.64, conflict-free
                wgp[j2] = *(const uint64_t*)&WGs[kk][j2 * 64 + 2 * tx];
            }
#pragma unroll
            for (int i = 0; i < 8; i++)
#pragma unroll
                for (int j2 = 0; j2 < 2; j2++) {
                    fma_x2(acc1p[i][j2], xp[i], w1p[j2]);
                    fma_x2(accgp[i][j2], xp[i], wgp[j2]);
                }
        }
        __syncthreads();
    }

    // GLU epilogue -> h tile into smem (per-element identical to scalar version)
#pragma unroll
    for (int i = 0; i < 8; i++) {
        int r = i * 8 + ty;
#pragma unroll
        for (int j2 = 0; j2 < 2; j2++) {
            int n = j2 * 64 + 2 * tx;
            uint32_t alo, ahi, glo, ghi;
            asm("mov.b64 {%0, %1}, %2;" : "=r"(alo), "=r"(ahi) : "l"(acc1p[i][j2]));
            asm("mov.b64 {%0, %1}, %2;" : "=r"(glo), "=r"(ghi) : "l"(accgp[i][j2]));
            float a0 = __uint_as_float(alo) + b1[n];
            float a1 = __uint_as_float(ahi) + b1[n + 1];
            float g0 = fmaxf(__uint_as_float(glo) + bg[n],     0.f);
            float g1 = fmaxf(__uint_as_float(ghi) + bg[n + 1], 0.f);
            float2 hv;
            hv.x = fmaxf(a0 * g0, 0.f);
            hv.y = fmaxf(a1 * g1, 0.f);
            *(float2*)&Hs[r][n] = hv;
        }
    }
    for (int i = tid; i < Hdim * Ecnt; i += 256) W2s[i] = w2[i];
    __syncthreads();

    // logits for 64 rows: thread (r = tid>>2, q = tid&3) sums 32 n's, then
    // 4-lane shuffle reduce.
    {
        const int r = tid >> 2;
        const int q = tid & 3;
        float acc[Ecnt];
#pragma unroll
        for (int e = 0; e < Ecnt; e++) acc[e] = 0.f;
#pragma unroll 4
        for (int k = 0; k < 32; k++) {
            int n = q * 32 + k;
            float hv = Hs[r][n];
#pragma unroll
            for (int e = 0; e < Ecnt; e++)
                acc[e] = fmaf(hv, W2s[n * Ecnt + e], acc[e]);
        }
#pragma unroll
        for (int e = 0; e < Ecnt; e++) {
            acc[e] += __shfl_xor_sync(0xffffffffu, acc[e], 1);
            acc[e] += __shfl_xor_sync(0xffffffffu, acc[e], 2);
        }
        if (q == 0) {
#pragma unroll
            for (int e = 0; e < Ecnt; e++)
                g_logits[(size_t)(row0 + r) * Ecnt + e] = acc[e] + b2[e];
        }
    }
}

// ---------------------------------------------------------------------------
// Kernel 3: per expert — column softmax, exact top-2048 (radix bisection).
// ---------------------------------------------------------------------------
#define EQ_CAP 1024
__global__ __launch_bounds__(1024) void k_select()
{
    __shared__ float lv[Bsz];
    __shared__ float s_warp[32];
    __shared__ int   s_bits[32];
    __shared__ unsigned s_cnt;
    __shared__ int   s_eq[EQ_CAP];
    __shared__ unsigned s_eqn;
    __shared__ float s_bf;

    const int e    = blockIdx.x;
    const int tid  = threadIdx.x;
    const int lane = tid & 31;
    const int wid  = tid >> 5;

    float loc[8];
#pragma unroll
    for (int r = 0; r < 8; r++) {
        int i = tid * 8 + r;
        loc[r] = g_logits[(size_t)i * Ecnt + e];
        g_sel_slot[i][e] = -1;
    }
    if (tid < 32) s_bits[tid] = 0;
    if (tid == 0) { s_cnt = 0u; s_eqn = 0u; }

    float m = loc[0];
#pragma unroll
    for (int r = 1; r < 8; r++) m = fmaxf(m, loc[r]);
#pragma unroll
    for (int o = 16; o > 0; o >>= 1) m = fmaxf(m, __shfl_xor_sync(0xffffffffu, m, o));
    if (lane == 0) s_warp[wid] = m;
    __syncthreads();
    if (tid < 32) {
        float v = s_warp[tid];
#pragma unroll
        for (int o = 16; o > 0; o >>= 1) v = fmaxf(v, __shfl_xor_sync(0xffffffffu, v, o));
        if (tid == 0) s_bf = v;
    }
    __syncthreads();
    m = s_bf;
    __syncthreads();

    float s = 0.f;
#pragma unroll
    for (int r = 0; r < 8; r++) s += expf(loc[r] - m);
#pragma unroll
    for (int o = 16; o > 0; o >>= 1) s += __shfl_xor_sync(0xffffffffu, s, o);
    if (lane == 0) s_warp[wid] = s;
    __syncthreads();
    if (tid < 32) {
        float v = s_warp[tid];
#pragma unroll
        for (int o = 16; o > 0; o >>= 1) v += __shfl_xor_sync(0xffffffffu, v, o);
        if (tid == 0) s_bf = v;
    }
    __syncthreads();
    s = s_bf;
    __syncthreads();

    const float inv_s = 1.0f / s;
    unsigned ub[8];
#pragma unroll
    for (int r = 0; r < 8; r++) {
        float v = expf(loc[r] - m) * inv_s;
        lv[tid * 8 + r] = v;
        ub[r] = __float_as_uint(v);
    }
    __syncthreads();

    unsigned cur = 0u;
    for (int bit = 29; bit >= 0; bit--) {
        unsigned cand = cur | (1u << bit);
        int c = 0;
#pragma unroll
        for (int r = 0; r < 8; r++) c += (ub[r] >= cand) ? 1 : 0;
#pragma unroll
        for (int o = 16; o > 0; o >>= 1) c += __shfl_xor_sync(0xffffffffu, c, o);
        if (lane == 0) atomicAdd(&s_bits[bit], c);
        __syncthreads();
        if (s_bits[bit] >= BKSEL) cur = cand;
    }
    const unsigned V = cur;

#pragma unroll
    for (int r = 0; r < 8; r++) {
        int i = tid * 8 + r;
        if (ub[r] > V) {
            unsigned p = atomicAdd(&s_cnt, 1u);
            g_idx[e][p] = i;
            g_sel_slot[i][e] = (int)p;
        } else if (ub[r] == V) {
            unsigned q = atomicAdd(&s_eqn, 1u);
            if (q < EQ_CAP) s_eq[q] = i;
        }
    }
    __syncthreads();

    const unsigned n_greater = s_cnt;
    const unsigned needed    = BKSEL - n_greater;
    const unsigned eqn       = s_eqn;

    if (eqn == needed && eqn <= EQ_CAP) {
        for (unsigned q = tid; q < eqn; q += 1024) {
            int i = s_eq[q];
            unsigned p = n_greater + q;
            g_idx[e][p] = i;
            g_sel_slot[i][e] = (int)p;
        }
    } else if (tid == 0) {
        unsigned p = n_greater;
        for (int i = 0; i < Bsz && p < BKSEL; i++) {
            if (__float_as_uint(lv[i]) == V) {
                g_idx[e][p] = i;
                g_sel_slot[i][e] = (int)p;
                p++;
            }
        }
    }
    __syncthreads();

    float wsv[2];
    float m2 = -1e30f;
#pragma unroll
    for (int r = 0; r < 2; r++) {
        int slot = tid + r * 1024;
        wsv[r] = lv[g_idx[e][slot]];
        m2 = fmaxf(m2, wsv[r]);
    }
#pragma unroll
    for (int o = 16; o > 0; o >>= 1) m2 = fmaxf(m2, __shfl_xor_sync(0xffffffffu, m2, o));
    if (lane == 0) s_warp[wid] = m2;
    __syncthreads();
    if (tid < 32) {
        float v = s_warp[tid];
#pragma unroll
        for (int o = 16; o > 0; o >>= 1) v = fmaxf(v, __shfl_xor_sync(0xffffffffu, v, o));
        if (tid == 0) s_bf = v;
    }
    __syncthreads();
    m2 = s_bf;
    __syncthreads();

    float s2 = expf(wsv[0] - m2) + expf(wsv[1] - m2);
#pragma unroll
    for (int o = 16; o > 0; o >>= 1) s2 += __shfl_xor_sync(0xffffffffu, s2, o);
    if (lane == 0) s_warp[wid] = s2;
    __syncthreads();
    if (tid < 32) {
        float v = s_warp[tid];
#pragma unroll
        for (int o = 16; o > 0; o >>= 1) v += __shfl_xor_sync(0xffffffffu, v, o);
        if (tid == 0) s_bf = v;
    }
    __syncthreads();
    s2 = s_bf;

    const float inv_s2 = 1.0f / s2;
#pragma unroll
    for (int r = 0; r < 2; r++)
        g_nws[e][tid + r * 1024] = expf(wsv[r] - m2) * inv_s2;
}

// ---------------------------------------------------------------------------
// Kernel 4: expert GEMM on tensor cores (tf32 mma.sync m16n8k8) — R8 proven.
//   eo[slot, e, :] = (x[idx[e][slot]] @ we[e] + be[e]) * nws[e][slot]
// Pre-rounded operands; 128x128 tile, kb=16, 3-stage cp.async ring, ONE
// __syncthreads per iteration; 8 warps (2m x 4n), 64x32/warp.
// ---------------------------------------------------------------------------
__global__ __launch_bounds__(256, 2) void k_expert(
    const float* __restrict__ be)
{
    __shared__ float As[3][128][20];
    __shared__ float Bs[3][16][136];
    __shared__ int   ridx[128];

    const int e  = blockIdx.z;
    const int m0 = blockIdx.y * 128;
    const int n0 = blockIdx.x * 128;
    const int tid  = threadIdx.x;
    const int lane = tid & 31;
    const int w    = tid >> 5;
    const int wm   = w & 1;
    const int wn   = w >> 1;
    const int g    = lane >> 2;
    const int c    = lane & 3;

    if (tid < 128) ridx[tid] = g_idx[e][m0 + tid];
    __syncthreads();

    const float* weE = g_wt + (size_t)e * DIN * DOUT + n0;

    float acc[4][4][4];
#pragma unroll
    for (int mi = 0; mi < 4; mi++)
#pragma unroll
        for (int nj = 0; nj < 4; nj++)
#pragma unroll
            for (int q = 0; q < 4; q++) acc[mi][nj][q] = 0.f;

#define LOAD_STAGE(buf, k0)                                                    \
    do {                                                                       \
        _Pragma("unroll")                                                      \
        for (int s_ = 0; s_ < 2; s_++) {                                       \
            int lin = tid + s_ * 256;                                          \
            int row = lin >> 2, col = (lin & 3) << 2;                          \
            cp_async16(&As[buf][row][col],                                     \
                       g_xt + (size_t)ridx[row] * DIN + (k0) + col);           \
        }                                                                      \
        _Pragma("unroll")                                                      \
        for (int s_ = 0; s_ < 2; s_++) {                                       \
            int lin = tid + s_ * 256;                                          \
            int kk_ = lin >> 5, col = (lin & 31) << 2;                         \
            cp_async16(&Bs[buf][kk_][col],                                     \
                       weE + (size_t)((k0) + kk_) * DOUT + col);               \
        }                                                                      \
        asm volatile("cp.async.commit_group;\n");                              \
    } while (0)

    LOAD_STAGE(0, 0);
    LOAD_STAGE(1, 16);

    const int NT = DIN / 16;
    int buf = 0, nbuf = 2;
    for (int t = 0; t < NT; t++) {
        if (t + 2 < NT) {
            asm volatile("cp.async.wait_group 1;\n");
            __syncthreads();
            LOAD_STAGE(nbuf, (t + 2) * 16);
        } else {
            asm volatile("cp.async.wait_group 0;\n");
            __syncthreads();
        }

#pragma unroll
        for (int kk = 0; kk < 2; kk++) {
            uint32_t aF[4][4];
            uint32_t bF[4][2];
            const int kb8 = kk * 8;
#pragma unroll
            for (int mi = 0; mi < 4; mi++) {
                int row = wm * 64 + mi * 16 + g;
                aF[mi][0] = __float_as_uint(As[buf][row    ][kb8 + c    ]);
                aF[mi][1] = __float_as_uint(As[buf][row + 8][kb8 + c    ]);
                aF[mi][2] = __float_as_uint(As[buf][row    ][kb8 + c + 4]);
                aF[mi][3] = __float_as_uint(As[buf][row + 8][kb8 + c + 4]);
            }
#pragma unroll
            for (int nj = 0; nj < 4; nj++) {
                int nn = wn * 32 + nj * 8 + g;
                bF[nj][0] = __float_as_uint(Bs[buf][kb8 + c    ][nn]);
                bF[nj][1] = __float_as_uint(Bs[buf][kb8 + c + 4][nn]);
            }
#pragma unroll
            for (int mi = 0; mi < 4; mi++)
#pragma unroll
                for (int nj = 0; nj < 4; nj++)
                    mma_tf32(acc[mi][nj], aF[mi], bF[nj]);
        }
        buf++;  if (buf == 3)  buf = 0;
        nbuf++; if (nbuf == 3) nbuf = 0;
    }
#undef LOAD_STAGE

    const float* beE = be + (size_t)e * DOUT + n0;
#pragma unroll
    for (int mi = 0; mi < 4; mi++) {
        int slot0 = m0 + wm * 64 + mi * 16 + g;
        int slot1 = slot0 + 8;
        float nw0 = g_nws[e][slot0];
        float nw1 = g_nws[e][slot1];
        float* o0 = g_eo + ((size_t)slot0 * Ecnt + e) * DOUT + n0;
        float* o1 = g_eo + ((size_t)slot1 * Ecnt + e) * DOUT + n0;
#pragma unroll
        for (int nj = 0; nj < 4; nj++) {
            int n = wn * 32 + nj * 8 + c * 2;
            float bb0 = beE[n], bb1 = beE[n + 1];
            float2 v0, v1;
            v0.x = (acc[mi][nj][0] + bb0) * nw0;
            v0.y = (acc[mi][nj][1] + bb1) * nw0;
            v1.x = (acc[mi][nj][2] + bb0) * nw1;
            v1.y = (acc[mi][nj][3] + bb1) * nw1;
            *(float2*)(o0 + n) = v0;
            *(float2*)(o1 + n) = v1;
        }
    }
}

// ---------------------------------------------------------------------------
// Kernel 5: combine (float4). out[b, e*DOUT+d] = c_e[d] + sum_e' c_e'[d]
// ---------------------------------------------------------------------------
__global__ __launch_bounds__(256) void k_combine(float* __restrict__ out)
{
    __shared__ int slots[Ecnt];
    const int b   = blockIdx.x;
    const int tid = threadIdx.x;
    if (tid < Ecnt) slots[tid] = g_sel_slot[b][tid];
    __syncthreads();

    const int d = tid * 4;
    float4 cv[Ecnt];
    float4 ssum = make_float4(0.f, 0.f, 0.f, 0.f);
#pragma unroll
    for (int e = 0; e < Ecnt; e++) {
        int slot = slots[e];
        float4 v = make_float4(0.f, 0.f, 0.f, 0.f);
        if (slot >= 0)
            v = *(const float4*)(g_eo + ((size_t)slot * Ecnt + e) * DOUT + d);
        cv[e] = v;
        ssum.x += v.x; ssum.y += v.y; ssum.z += v.z; ssum.w += v.w;
    }
    float* orow = out + (size_t)b * (Ecnt * DOUT) + d;
#pragma unroll
    for (int e = 0; e < Ecnt; e++) {
        float4 o;
        o.x = cv[e].x + ssum.x;
        o.y = cv[e].y + ssum.y;
        o.z = cv[e].z + ssum.z;
        o.w = cv[e].w + ssum.w;
        *(float4*)(orow + (size_t)e * DOUT) = o;
    }
}

// ---------------------------------------------------------------------------
extern "C" void kernel_launch(void* const* d_in, const int* in_sizes, int n_in,
                              void* d_out, int out_size)
{
    const float* x  = (const float*)d_in[0];
    const float* w1 = (const float*)d_in[1];
    const float* b1 = (const float*)d_in[2];
    const float* wg = (const float*)d_in[3];
    const float* bg = (const float*)d_in[4];
    const float* w2 = (const float*)d_in[5];
    const float* b2 = (const float*)d_in[6];
    const float* we = (const float*)d_in[7];
    const float* be = (const float*)d_in[8];
    float* out = (float*)d_out;

    k_cvtw<<<2048, 256>>>(we);
    k_router<<<Bsz / 64, 256>>>(x, w1, b1, wg, bg, w2, b2);
    k_select<<<Ecnt, 1024>>>();
    k_expert<<<dim3(DOUT / 128, BKSEL / 128, Ecnt), 256>>>(be);
    k_combine<<<Bsz, 256>>>(out);
}